// round 3
// baseline (speedup 1.0000x reference)
#include <cuda_runtime.h>

// ---------------------------------------------------------------------------
// Problem constants
// ---------------------------------------------------------------------------
constexpr int BB   = 8;
constexpr int NP   = 8192;
constexpr int SP   = 2048;
constexpr int CIN  = 256;     // points2 channels
constexpr int CSK  = 128;     // points1 channels (skip)
constexpr int C0   = 384;     // IN+SKIP
constexpr int C1   = 256;     // OUT
constexpr int CE   = 1024;    // OUT*EXP
constexpr int MTOT = BB * NP; // 65536 rows

// ---------------------------------------------------------------------------
// Scratch (device globals; no dynamic allocation allowed)
// ---------------------------------------------------------------------------
static __device__ float g_A1 [MTOT * C0];      // new_points, row-major [m, 384]
static __device__ float g_p2t[BB * SP * CIN];  // points2 transposed [b, s, c]
static __device__ float g_y1 [MTOT * C1];      // conv0 out (pre-GN)
static __device__ float g_h1 [MTOT * CE];      // conv1 out (pre-GN)
static __device__ float g_h2 [MTOT * C1];      // conv2 out (pre-GN)
static __device__ float g_sum[3 * 64];         // per-stage (b,g) sums
static __device__ float g_sqs[3 * 64];         // per-stage (b,g) sum-squares
static __device__ float g_cA0[BB * C1], g_cB0[BB * C1];
static __device__ float g_cA1[BB * CE], g_cB1[BB * CE];
static __device__ float g_cA2[BB * C1], g_cB2[BB * C1];
static __device__ float g_scale[BB * C1], g_shift[BB * C1];

__device__ __forceinline__ float silu_f(float x) {
    return __fdividef(x, 1.0f + __expf(-x));
}

// ---------------------------------------------------------------------------
// Zero the stats accumulators (must happen every launch)
// ---------------------------------------------------------------------------
__global__ void zero_k() {
    int i = threadIdx.x;
    if (i < 192) { g_sum[i] = 0.0f; g_sqs[i] = 0.0f; }
}

// ---------------------------------------------------------------------------
// Transpose points1 [B,128,N] -> g_A1 columns [0,128)   (row-major [m,384])
// ---------------------------------------------------------------------------
__global__ void tr_p1_k(const float* __restrict__ src) {
    __shared__ float t[32][33];
    int b  = blockIdx.z;
    int n0 = blockIdx.x * 32;
    int c0 = blockIdx.y * 32;
    int tx = threadIdx.x, ty = threadIdx.y;
#pragma unroll
    for (int i = 0; i < 4; i++) {
        int cl = ty + i * 8;
        t[cl][tx] = src[((size_t)b * CSK + (c0 + cl)) * NP + n0 + tx];
    }
    __syncthreads();
#pragma unroll
    for (int i = 0; i < 4; i++) {
        int nl = ty + i * 8;
        g_A1[((size_t)b * NP + (n0 + nl)) * C0 + c0 + tx] = t[tx][nl];
    }
}

// ---------------------------------------------------------------------------
// Transpose points2 [B,256,S] -> g_p2t [b, s, c]
// ---------------------------------------------------------------------------
__global__ void tr_p2_k(const float* __restrict__ src) {
    __shared__ float t[32][33];
    int b  = blockIdx.z;
    int s0 = blockIdx.x * 32;
    int c0 = blockIdx.y * 32;
    int tx = threadIdx.x, ty = threadIdx.y;
#pragma unroll
    for (int i = 0; i < 4; i++) {
        int cl = ty + i * 8;
        t[cl][tx] = src[((size_t)b * CIN + (c0 + cl)) * SP + s0 + tx];
    }
    __syncthreads();
#pragma unroll
    for (int i = 0; i < 4; i++) {
        int sl = ty + i * 8;
        g_p2t[((size_t)b * SP + (s0 + sl)) * CIN + c0 + tx] = t[tx][sl];
    }
}

// ---------------------------------------------------------------------------
// Embedding modulation: scale/shift [b,c]
// ---------------------------------------------------------------------------
__global__ void emb_k(const float* __restrict__ t_emb, const float* __restrict__ c_emb,
                      const float* __restrict__ tw, const float* __restrict__ tb,
                      const float* __restrict__ cw, const float* __restrict__ cb) {
    __shared__ float te[C1], ce[C1];
    int b = blockIdx.x;
    int j = threadIdx.x;  // 0..511
    if (j < C1) { te[j] = t_emb[b * C1 + j]; ce[j] = c_emb[b * C1 + j]; }
    __syncthreads();
    const float* twr = tw + (size_t)j * C1;
    const float* cwr = cw + (size_t)j * C1;
    float s = tb[j] + cb[j];
#pragma unroll 8
    for (int k = 0; k < C1; k++) s += te[k] * twr[k] + ce[k] * cwr[k];
    if (j < C1) g_scale[b * C1 + j] = s;
    else        g_shift[b * C1 + (j - C1)] = s;
}

// ---------------------------------------------------------------------------
// 3-NN + inverse-distance-weighted interpolation.
// Writes g_A1 columns [128,384).
// ---------------------------------------------------------------------------
__global__ void knn_k(const float* __restrict__ xyz1, const float* __restrict__ xyz2) {
    __shared__ float4 ref[SP];  // (x,y,z,|p|^2) per ref point : 32 KB
    int b = blockIdx.y;
    int n = blockIdx.x * 128 + threadIdx.x;
    for (int s = threadIdx.x; s < SP; s += 128) {
        float x = xyz2[((size_t)b * 3 + 0) * SP + s];
        float y = xyz2[((size_t)b * 3 + 1) * SP + s];
        float z = xyz2[((size_t)b * 3 + 2) * SP + s];
        ref[s] = make_float4(x, y, z, x * x + y * y + z * z);
    }
    __syncthreads();

    float px = xyz1[((size_t)b * 3 + 0) * NP + n];
    float py = xyz1[((size_t)b * 3 + 1) * NP + n];
    float pz = xyz1[((size_t)b * 3 + 2) * NP + n];
    float n1 = px * px + py * py + pz * pz;

    float d0 = 3.4e38f, d1 = 3.4e38f, d2 = 3.4e38f;
    int   i0 = 0, i1 = 0, i2 = 0;
    for (int s = 0; s < SP; s++) {
        float4 r = ref[s];
        float dot = px * r.x + py * r.y + pz * r.z;
        float d = (-2.0f * dot + n1) + r.w;   // same formula as reference
        if (d < d2) {
            if (d < d1) {
                d2 = d1; i2 = i1;
                if (d < d0) { d1 = d0; i1 = i0; d0 = d; i0 = s; }
                else        { d1 = d;  i1 = s; }
            } else { d2 = d; i2 = s; }
        }
    }

    float r0 = 1.0f / (d0 + 1e-8f);
    float r1 = 1.0f / (d1 + 1e-8f);
    float r2 = 1.0f / (d2 + 1e-8f);
    float rs = r0 + r1 + r2;
    float w0 = r0 / rs, w1 = r1 / rs, w2 = r2 / rs;

    const float4* p0 = (const float4*)&g_p2t[((size_t)b * SP + i0) * CIN];
    const float4* p1 = (const float4*)&g_p2t[((size_t)b * SP + i1) * CIN];
    const float4* p2 = (const float4*)&g_p2t[((size_t)b * SP + i2) * CIN];
    float4* dst = (float4*)&g_A1[((size_t)b * NP + n) * C0 + CSK];
#pragma unroll 4
    for (int c = 0; c < CIN / 4; c++) {
        float4 a = p0[c], bq = p1[c], cq = p2[c];
        float4 o;
        o.x = a.x * w0 + bq.x * w1 + cq.x * w2;
        o.y = a.y * w0 + bq.y * w1 + cq.y * w2;
        o.z = a.z * w0 + bq.z * w1 + cq.z * w2;
        o.w = a.w * w0 + bq.w * w1 + cq.w * w2;
        dst[c] = o;
    }
}

// ---------------------------------------------------------------------------
// GEMM: C[m,o] = sum_k f(A[m,k]) * W[o,k] + bias[o]
//   STAGE 0: A = g_A1 (raw)            -> g_y1, stats[0]
//   STAGE 1: A = silu(gn0(g_y1))       -> g_h1, stats[1]
//   STAGE 2: A = silu(gn1(g_h1))       -> g_h2, stats[2]
// BM=BN=128, BK=16, 256 threads, 8x8 micro-tile.
// ---------------------------------------------------------------------------
template <int K, int ON, int STAGE>
__global__ __launch_bounds__(256, 2) void gemm_k(const float* __restrict__ W,
                                                 const float* __restrict__ bias) {
    constexpr bool TRANSF = (STAGE > 0);
    __shared__ float As[16][128 + 4];
    __shared__ float Ws[16][128 + 4];

    const float* A  = (STAGE == 0) ? g_A1 : (STAGE == 1 ? g_y1 : g_h1);
    float*       Co = (STAGE == 0) ? g_y1 : (STAGE == 1 ? g_h1 : g_h2);

    const int tid = threadIdx.x;
    const int m0 = blockIdx.x * 128;
    const int n0 = blockIdx.y * 128;
    const int b  = m0 >> 13;  // NP = 8192

    const float* cA = nullptr;
    const float* cB = nullptr;
    if (TRANSF) {
        if (STAGE == 1) { cA = g_cA0 + b * K; cB = g_cB0 + b * K; }
        else            { cA = g_cA1 + b * K; cB = g_cB1 + b * K; }
    }

    const int warp = tid >> 5, lane = tid & 31;
    const int wr = warp & 3, wc = warp >> 2;
    const int lr = lane & 3, lc = lane >> 2;
    const int mBase = wr * 32 + lr * 8;
    const int nBase = wc * 64 + lc * 8;

    float acc[8][8];
#pragma unroll
    for (int i = 0; i < 8; i++)
#pragma unroll
        for (int j = 0; j < 8; j++) acc[i][j] = 0.0f;

    const int arow = tid >> 2;        // 0..63
    const int ac4  = (tid & 3) * 4;   // 0,4,8,12

    for (int k0 = 0; k0 < K; k0 += 16) {
#pragma unroll
        for (int l = 0; l < 2; l++) {
            int row = arow + l * 64;
            float4 v = *(const float4*)(&A[(size_t)(m0 + row) * K + k0 + ac4]);
            if (TRANSF) {
                v.x = silu_f(v.x * cA[k0 + ac4 + 0] + cB[k0 + ac4 + 0]);
                v.y = silu_f(v.y * cA[k0 + ac4 + 1] + cB[k0 + ac4 + 1]);
                v.z = silu_f(v.z * cA[k0 + ac4 + 2] + cB[k0 + ac4 + 2]);
                v.w = silu_f(v.w * cA[k0 + ac4 + 3] + cB[k0 + ac4 + 3]);
            }
            As[ac4 + 0][row] = v.x; As[ac4 + 1][row] = v.y;
            As[ac4 + 2][row] = v.z; As[ac4 + 3][row] = v.w;
            float4 u = *(const float4*)(&W[(size_t)(n0 + row) * K + k0 + ac4]);
            Ws[ac4 + 0][row] = u.x; Ws[ac4 + 1][row] = u.y;
            Ws[ac4 + 2][row] = u.z; Ws[ac4 + 3][row] = u.w;
        }
        __syncthreads();
#pragma unroll
        for (int kk = 0; kk < 16; kk++) {
            float a[8], w[8];
            *(float4*)&a[0] = *(const float4*)&As[kk][mBase];
            *(float4*)&a[4] = *(const float4*)&As[kk][mBase + 4];
            *(float4*)&w[0] = *(const float4*)&Ws[kk][nBase];
            *(float4*)&w[4] = *(const float4*)&Ws[kk][nBase + 4];
#pragma unroll
            for (int i = 0; i < 8; i++)
#pragma unroll
                for (int j = 0; j < 8; j++) acc[i][j] += a[i] * w[j];
        }
        __syncthreads();
    }

    // Epilogue: +bias, store, accumulate GN stats for this stage's output
    float bs[8];
#pragma unroll
    for (int j = 0; j < 8; j++) bs[j] = bias[n0 + nBase + j];

    float s = 0.0f, s2 = 0.0f;
#pragma unroll
    for (int i = 0; i < 8; i++) {
        float v[8];
#pragma unroll
        for (int j = 0; j < 8; j++) {
            v[j] = acc[i][j] + bs[j];
            s += v[j];
            s2 += v[j] * v[j];
        }
        float* dst = &Co[(size_t)(m0 + mBase + i) * ON + n0 + nBase];
        *(float4*)(dst)     = make_float4(v[0], v[1], v[2], v[3]);
        *(float4*)(dst + 4) = make_float4(v[4], v[5], v[6], v[7]);
    }
    // reduce (s,s2) over each 16-lane half (all lanes in a half share (b,group))
#pragma unroll
    for (int off = 8; off >= 1; off >>= 1) {
        s  += __shfl_xor_sync(0xffffffffu, s,  off);
        s2 += __shfl_xor_sync(0xffffffffu, s2, off);
    }
    if ((lane & 15) == 0) {
        int chunk = n0 + wc * 64 + ((lane >> 4) << 5);
        int g = chunk / (ON / 8);
        atomicAdd(&g_sum[STAGE * 64 + b * 8 + g], s);
        atomicAdd(&g_sqs[STAGE * 64 + b * 8 + g], s2);
    }
}

// ---------------------------------------------------------------------------
// Finalize GN stats -> per-(b,c) affine coefs: x*a + bb == gn(x)*gw+gb
// ---------------------------------------------------------------------------
template <int STAGE, int CCH>
__global__ void finalize_k(const float* __restrict__ gw, const float* __restrict__ gb) {
    int b = blockIdx.x, c = threadIdx.x;
    int g = c / (CCH / 8);
    float cnt  = (float)(CCH / 8) * (float)NP;
    float mean = g_sum[STAGE * 64 + b * 8 + g] / cnt;
    float var  = g_sqs[STAGE * 64 + b * 8 + g] / cnt - mean * mean;
    float rstd = rsqrtf(var + 1e-5f);
    float a  = rstd * gw[c];
    float bb = gb[c] - mean * a;
    if      (STAGE == 0) { g_cA0[b * CCH + c] = a; g_cB0[b * CCH + c] = bb; }
    else if (STAGE == 1) { g_cA1[b * CCH + c] = a; g_cB1[b * CCH + c] = bb; }
    else                 { g_cA2[b * CCH + c] = a; g_cB2[b * CCH + c] = bb; }
}

// ---------------------------------------------------------------------------
// Final: out[b,c,n] = gn2(h2)*(1+scale)+shift + silu(gn0(y1))  (with transpose)
// ---------------------------------------------------------------------------
__global__ void final_k(float* __restrict__ out) {
    __shared__ float t[32][33];
    int b  = blockIdx.z;
    int n0 = blockIdx.x * 32;
    int c0 = blockIdx.y * 32;
    int tx = threadIdx.x, ty = threadIdx.y;
#pragma unroll
    for (int i = 0; i < 4; i++) {
        int nl = ty + i * 8;
        size_t m = (size_t)b * NP + n0 + nl;
        int c = c0 + tx;
        float h2 = g_h2[m * C1 + c];
        float hn = h2 * g_cA2[b * C1 + c] + g_cB2[b * C1 + c];
        float y1 = g_y1[m * C1 + c];
        float idn = silu_f(y1 * g_cA0[b * C1 + c] + g_cB0[b * C1 + c]);
        float v = hn * (1.0f + g_scale[b * C1 + c]) + g_shift[b * C1 + c] + idn;
        t[nl][tx] = v;
    }
    __syncthreads();
#pragma unroll
    for (int i = 0; i < 4; i++) {
        int cl = ty + i * 8;
        out[((size_t)b * C1 + c0 + cl) * NP + n0 + tx] = t[tx][cl];
    }
}

// ---------------------------------------------------------------------------
// Launch
// ---------------------------------------------------------------------------
extern "C" void kernel_launch(void* const* d_in, const int* in_sizes, int n_in,
                              void* d_out, int out_size) {
    (void)in_sizes; (void)n_in; (void)out_size;
    const float* xyz1    = (const float*)d_in[0];
    const float* points1 = (const float*)d_in[1];
    const float* xyz2    = (const float*)d_in[2];
    const float* points2 = (const float*)d_in[3];
    const float* t_emb   = (const float*)d_in[4];
    const float* c_emb   = (const float*)d_in[5];
    const float* mlp_w   = (const float*)d_in[6];
    const float* mlp_b   = (const float*)d_in[7];
    const float* mlp_gw  = (const float*)d_in[8];
    const float* mlp_gb  = (const float*)d_in[9];
    const float* c1w     = (const float*)d_in[10];
    const float* c1b     = (const float*)d_in[11];
    const float* g1w     = (const float*)d_in[12];
    const float* g1b     = (const float*)d_in[13];
    const float* c2w     = (const float*)d_in[14];
    const float* c2b     = (const float*)d_in[15];
    const float* g2w     = (const float*)d_in[16];
    const float* g2b     = (const float*)d_in[17];
    const float* tw      = (const float*)d_in[18];
    const float* tb      = (const float*)d_in[19];
    const float* cw      = (const float*)d_in[20];
    const float* cb      = (const float*)d_in[21];
    float* out = (float*)d_out;

    zero_k<<<1, 256>>>();
    tr_p1_k<<<dim3(NP / 32, CSK / 32, BB), dim3(32, 8)>>>(points1);
    tr_p2_k<<<dim3(SP / 32, CIN / 32, BB), dim3(32, 8)>>>(points2);
    emb_k<<<BB, 512>>>(t_emb, c_emb, tw, tb, cw, cb);
    knn_k<<<dim3(NP / 128, BB), 128>>>(xyz1, xyz2);

    gemm_k<C0, C1, 0><<<dim3(MTOT / 128, C1 / 128), 256>>>(mlp_w, mlp_b);
    finalize_k<0, C1><<<BB, C1>>>(mlp_gw, mlp_gb);

    gemm_k<C1, CE, 1><<<dim3(MTOT / 128, CE / 128), 256>>>(c1w, c1b);
    finalize_k<1, CE><<<BB, CE>>>(g1w, g1b);

    gemm_k<CE, C1, 2><<<dim3(MTOT / 128, C1 / 128), 256>>>(c2w, c2b);
    finalize_k<2, C1><<<BB, C1>>>(g2w, g2b);

    final_k<<<dim3(NP / 32, C1 / 32, BB), dim3(32, 8)>>>(out);
}

// round 4
// speedup vs baseline: 1.3631x; 1.3631x over previous
#include <cuda_runtime.h>
#include <cuda_bf16.h>
#include <cstdint>

// ---------------------------------------------------------------------------
// Problem constants
// ---------------------------------------------------------------------------
constexpr int BB   = 8;
constexpr int NP   = 8192;
constexpr int SP   = 2048;
constexpr int CIN  = 256;     // points2 channels
constexpr int CSK  = 128;     // points1 channels (skip)
constexpr int C0   = 384;     // IN+SKIP
constexpr int C1   = 256;     // OUT
constexpr int CE   = 1024;    // OUT*EXP
constexpr int MTOT = BB * NP; // 65536 rows

// ---------------------------------------------------------------------------
// Scratch (device globals; no dynamic allocation allowed)
// ---------------------------------------------------------------------------
static __device__ float g_A1 [MTOT * C0];      // new_points, row-major [m, 384]
static __device__ float g_p2t[BB * SP * CIN];  // points2 transposed [b, s, c]
static __device__ float g_y1 [MTOT * C1];      // conv0 out (pre-GN)
static __device__ float g_h1 [MTOT * CE];      // conv1 out (pre-GN)
static __device__ float g_h2 [MTOT * C1];      // conv2 out (pre-GN)
static __device__ float g_sum[3 * 64];         // per-stage (b,g) sums
static __device__ float g_sqs[3 * 64];         // per-stage (b,g) sum-squares
static __device__ float g_cA0[BB * C1], g_cB0[BB * C1];
static __device__ float g_cA1[BB * CE], g_cB1[BB * CE];
static __device__ float g_cA2[BB * C1], g_cB2[BB * C1];
static __device__ float g_scale[BB * C1], g_shift[BB * C1];

__device__ __forceinline__ float silu_f(float x) {
    return __fdividef(x, 1.0f + __expf(-x));
}

// ---------------------------------------------------------------------------
// MMA helpers (sm_80-style bf16 tensor core path, valid on sm_100a)
// ---------------------------------------------------------------------------
__device__ __forceinline__ uint32_t sptr(const void* p) {
    return (uint32_t)__cvta_generic_to_shared(p);
}
__device__ __forceinline__ void ldmx4(uint32_t* r, uint32_t addr) {
    asm volatile("ldmatrix.sync.aligned.m8n8.x4.shared.b16 {%0,%1,%2,%3}, [%4];\n"
                 : "=r"(r[0]), "=r"(r[1]), "=r"(r[2]), "=r"(r[3]) : "r"(addr));
}
__device__ __forceinline__ void mma16816(float* c, const uint32_t* a, const uint32_t* b) {
    asm volatile(
        "mma.sync.aligned.m16n8k16.row.col.f32.bf16.bf16.f32 "
        "{%0,%1,%2,%3}, {%4,%5,%6,%7}, {%8,%9}, {%0,%1,%2,%3};\n"
        : "+f"(c[0]), "+f"(c[1]), "+f"(c[2]), "+f"(c[3])
        : "r"(a[0]), "r"(a[1]), "r"(a[2]), "r"(a[3]), "r"(b[0]), "r"(b[1]));
}

// ---------------------------------------------------------------------------
// Zero the stats accumulators (must happen every launch)
// ---------------------------------------------------------------------------
__global__ void zero_k() {
    int i = threadIdx.x;
    if (i < 192) { g_sum[i] = 0.0f; g_sqs[i] = 0.0f; }
}

// ---------------------------------------------------------------------------
// Transpose points1 [B,128,N] -> g_A1 columns [0,128)   (row-major [m,384])
// ---------------------------------------------------------------------------
__global__ void tr_p1_k(const float* __restrict__ src) {
    __shared__ float t[32][33];
    int b  = blockIdx.z;
    int n0 = blockIdx.x * 32;
    int c0 = blockIdx.y * 32;
    int tx = threadIdx.x, ty = threadIdx.y;
#pragma unroll
    for (int i = 0; i < 4; i++) {
        int cl = ty + i * 8;
        t[cl][tx] = src[((size_t)b * CSK + (c0 + cl)) * NP + n0 + tx];
    }
    __syncthreads();
#pragma unroll
    for (int i = 0; i < 4; i++) {
        int nl = ty + i * 8;
        g_A1[((size_t)b * NP + (n0 + nl)) * C0 + c0 + tx] = t[tx][nl];
    }
}

// ---------------------------------------------------------------------------
// Transpose points2 [B,256,S] -> g_p2t [b, s, c]
// ---------------------------------------------------------------------------
__global__ void tr_p2_k(const float* __restrict__ src) {
    __shared__ float t[32][33];
    int b  = blockIdx.z;
    int s0 = blockIdx.x * 32;
    int c0 = blockIdx.y * 32;
    int tx = threadIdx.x, ty = threadIdx.y;
#pragma unroll
    for (int i = 0; i < 4; i++) {
        int cl = ty + i * 8;
        t[cl][tx] = src[((size_t)b * CIN + (c0 + cl)) * SP + s0 + tx];
    }
    __syncthreads();
#pragma unroll
    for (int i = 0; i < 4; i++) {
        int sl = ty + i * 8;
        g_p2t[((size_t)b * SP + (s0 + sl)) * CIN + c0 + tx] = t[tx][sl];
    }
}

// ---------------------------------------------------------------------------
// Embedding modulation: one warp per (b, output-row j) -> full-chip parallel
// ---------------------------------------------------------------------------
__global__ void emb_k(const float* __restrict__ t_emb, const float* __restrict__ c_emb,
                      const float* __restrict__ tw, const float* __restrict__ tb,
                      const float* __restrict__ cw, const float* __restrict__ cb) {
    int gw   = (blockIdx.x * blockDim.x + threadIdx.x) >> 5;  // 0..4095
    int lane = threadIdx.x & 31;
    int b = gw >> 9;        // 512 outputs per batch
    int j = gw & 511;       // 0..511
    const float* twr = tw + (size_t)j * C1;
    const float* cwr = cw + (size_t)j * C1;
    const float* te  = t_emb + b * C1;
    const float* ce  = c_emb + b * C1;
    int k0 = lane * 8;
    float4 a0 = *(const float4*)(twr + k0);
    float4 a1 = *(const float4*)(twr + k0 + 4);
    float4 b0 = *(const float4*)(cwr + k0);
    float4 b1 = *(const float4*)(cwr + k0 + 4);
    float4 t0 = *(const float4*)(te + k0);
    float4 t1 = *(const float4*)(te + k0 + 4);
    float4 c0 = *(const float4*)(ce + k0);
    float4 c1 = *(const float4*)(ce + k0 + 4);
    float s = a0.x * t0.x + a0.y * t0.y + a0.z * t0.z + a0.w * t0.w
            + a1.x * t1.x + a1.y * t1.y + a1.z * t1.z + a1.w * t1.w
            + b0.x * c0.x + b0.y * c0.y + b0.z * c0.z + b0.w * c0.w
            + b1.x * c1.x + b1.y * c1.y + b1.z * c1.z + b1.w * c1.w;
#pragma unroll
    for (int off = 16; off >= 1; off >>= 1) s += __shfl_xor_sync(0xffffffffu, s, off);
    if (lane == 0) {
        s += tb[j] + cb[j];
        if (j < C1) g_scale[b * C1 + j] = s;
        else        g_shift[b * C1 + (j - C1)] = s;
    }
}

// ---------------------------------------------------------------------------
// 3-NN + inverse-distance-weighted interpolation. Writes g_A1 cols [128,384).
// ---------------------------------------------------------------------------
__global__ void knn_k(const float* __restrict__ xyz1, const float* __restrict__ xyz2) {
    __shared__ float4 ref[SP];  // (x,y,z,|p|^2) per ref point : 32 KB
    int b = blockIdx.y;
    int n = blockIdx.x * 128 + threadIdx.x;
    for (int s = threadIdx.x; s < SP; s += 128) {
        float x = xyz2[((size_t)b * 3 + 0) * SP + s];
        float y = xyz2[((size_t)b * 3 + 1) * SP + s];
        float z = xyz2[((size_t)b * 3 + 2) * SP + s];
        ref[s] = make_float4(x, y, z, x * x + y * y + z * z);
    }
    __syncthreads();

    float px = xyz1[((size_t)b * 3 + 0) * NP + n];
    float py = xyz1[((size_t)b * 3 + 1) * NP + n];
    float pz = xyz1[((size_t)b * 3 + 2) * NP + n];
    float n1 = px * px + py * py + pz * pz;

    float d0 = 3.4e38f, d1 = 3.4e38f, d2 = 3.4e38f;
    int   i0 = 0, i1 = 0, i2 = 0;
    for (int s = 0; s < SP; s++) {
        float4 r = ref[s];
        float dot = px * r.x + py * r.y + pz * r.z;
        float d = (-2.0f * dot + n1) + r.w;   // same formula as reference
        if (d < d2) {
            if (d < d1) {
                d2 = d1; i2 = i1;
                if (d < d0) { d1 = d0; i1 = i0; d0 = d; i0 = s; }
                else        { d1 = d;  i1 = s; }
            } else { d2 = d; i2 = s; }
        }
    }

    float r0 = 1.0f / (d0 + 1e-8f);
    float r1 = 1.0f / (d1 + 1e-8f);
    float r2 = 1.0f / (d2 + 1e-8f);
    float rs = r0 + r1 + r2;
    float w0 = r0 / rs, w1 = r1 / rs, w2 = r2 / rs;

    const float4* p0 = (const float4*)&g_p2t[((size_t)b * SP + i0) * CIN];
    const float4* p1 = (const float4*)&g_p2t[((size_t)b * SP + i1) * CIN];
    const float4* p2 = (const float4*)&g_p2t[((size_t)b * SP + i2) * CIN];
    float4* dst = (float4*)&g_A1[((size_t)b * NP + n) * C0 + CSK];
#pragma unroll 4
    for (int c = 0; c < CIN / 4; c++) {
        float4 a = p0[c], bq = p1[c], cq = p2[c];
        float4 o;
        o.x = a.x * w0 + bq.x * w1 + cq.x * w2;
        o.y = a.y * w0 + bq.y * w1 + cq.y * w2;
        o.z = a.z * w0 + bq.z * w1 + cq.z * w2;
        o.w = a.w * w0 + bq.w * w1 + cq.w * w2;
        dst[c] = o;
    }
}

// ---------------------------------------------------------------------------
// Tensor-core GEMM with fp32 emulation via bf16 hi/lo split (3 products).
//   C[m,o] = sum_k f(A[m,k]) * W[o,k] + bias[o]
//   STAGE 0: A = g_A1 (raw)      -> g_y1, stats[0]
//   STAGE 1: A = silu(gn0(g_y1)) -> g_h1, stats[1]
//   STAGE 2: A = silu(gn1(g_h1)) -> g_h2, stats[2]
// BM=BN=128, BK=32, 256 threads (8 warps: 2m x 4n, 64x32 warp tile).
// ---------------------------------------------------------------------------
constexpr int ASTR = 40;  // smem row stride (bf16): 8 rows x 80B hit distinct banks

template <int K, int ON, int STAGE>
__global__ __launch_bounds__(256) void gemm_k(const float* __restrict__ W,
                                              const float* __restrict__ bias) {
    constexpr bool TRANSF = (STAGE > 0);
    constexpr int NB = K / 32;

    __shared__ __nv_bfloat16 sAhi[128][ASTR], sAlo[128][ASTR];
    __shared__ __nv_bfloat16 sWhi[128][ASTR], sWlo[128][ASTR];

    const float* A  = (STAGE == 0) ? g_A1 : (STAGE == 1 ? g_y1 : g_h1);
    float*       Co = (STAGE == 0) ? g_y1 : (STAGE == 1 ? g_h1 : g_h2);

    const int tid  = threadIdx.x;
    const int m0   = blockIdx.x * 128;
    const int n0   = blockIdx.y * 128;
    const int b    = m0 >> 13;  // NP = 8192
    const int lane = tid & 31;
    const int warp = tid >> 5;
    const int wm   = (warp & 1) * 64;   // warp m-offset
    const int wn   = (warp >> 1) * 32;  // warp n-offset

    const float* cA = nullptr;
    const float* cB = nullptr;
    if (TRANSF) {
        if (STAGE == 1) { cA = g_cA0 + b * K; cB = g_cB0 + b * K; }
        else            { cA = g_cA1 + b * K; cB = g_cB1 + b * K; }
    }

    // global->reg staging: each thread owns (row = tid>>1, khalf = (tid&1)*16)
    const int grow = tid >> 1;
    const int kh   = (tid & 1) * 16;

    float4 pa[4], pw[4];
    auto load_blk = [&](int k0) {
        const float4* ap = (const float4*)(A + (size_t)(m0 + grow) * K + k0 + kh);
        const float4* wp = (const float4*)(W + (size_t)(n0 + grow) * K + k0 + kh);
#pragma unroll
        for (int q = 0; q < 4; q++) { pa[q] = ap[q]; pw[q] = wp[q]; }
    };
    auto store_blk = [&](int k0) {
#pragma unroll
        for (int q = 0; q < 4; q++) {
            float4 v = pa[q];
            if (TRANSF) {
                int kk = k0 + kh + q * 4;
                v.x = silu_f(v.x * __ldg(cA + kk + 0) + __ldg(cB + kk + 0));
                v.y = silu_f(v.y * __ldg(cA + kk + 1) + __ldg(cB + kk + 1));
                v.z = silu_f(v.z * __ldg(cA + kk + 2) + __ldg(cB + kk + 2));
                v.w = silu_f(v.w * __ldg(cA + kk + 3) + __ldg(cB + kk + 3));
            }
            __nv_bfloat16 hx = __float2bfloat16(v.x), hy = __float2bfloat16(v.y);
            __nv_bfloat16 hz = __float2bfloat16(v.z), hw = __float2bfloat16(v.w);
            __nv_bfloat16 lx = __float2bfloat16(v.x - __bfloat162float(hx));
            __nv_bfloat16 ly = __float2bfloat16(v.y - __bfloat162float(hy));
            __nv_bfloat16 lz = __float2bfloat16(v.z - __bfloat162float(hz));
            __nv_bfloat16 lw = __float2bfloat16(v.w - __bfloat162float(hw));
            int c4 = kh + q * 4;
            *(__nv_bfloat162*)&sAhi[grow][c4]     = __halves2bfloat162(hx, hy);
            *(__nv_bfloat162*)&sAhi[grow][c4 + 2] = __halves2bfloat162(hz, hw);
            *(__nv_bfloat162*)&sAlo[grow][c4]     = __halves2bfloat162(lx, ly);
            *(__nv_bfloat162*)&sAlo[grow][c4 + 2] = __halves2bfloat162(lz, lw);

            float4 u = pw[q];
            __nv_bfloat16 ux = __float2bfloat16(u.x), uy = __float2bfloat16(u.y);
            __nv_bfloat16 uz = __float2bfloat16(u.z), uw = __float2bfloat16(u.w);
            __nv_bfloat16 vx = __float2bfloat16(u.x - __bfloat162float(ux));
            __nv_bfloat16 vy = __float2bfloat16(u.y - __bfloat162float(uy));
            __nv_bfloat16 vz = __float2bfloat16(u.z - __bfloat162float(uz));
            __nv_bfloat16 vw = __float2bfloat16(u.w - __bfloat162float(uw));
            *(__nv_bfloat162*)&sWhi[grow][c4]     = __halves2bfloat162(ux, uy);
            *(__nv_bfloat162*)&sWhi[grow][c4 + 2] = __halves2bfloat162(uz, uw);
            *(__nv_bfloat162*)&sWlo[grow][c4]     = __halves2bfloat162(vx, vy);
            *(__nv_bfloat162*)&sWlo[grow][c4 + 2] = __halves2bfloat162(vz, vw);
        }
    };

    float c[4][4][4];
#pragma unroll
    for (int i = 0; i < 4; i++)
#pragma unroll
        for (int j = 0; j < 4; j++)
#pragma unroll
            for (int r = 0; r < 4; r++) c[i][j][r] = 0.0f;

    // ldmatrix per-lane addressing (row = lane&15, k-half = (lane>>4)*8)
    const int lr15 = lane & 15;
    const int lk8  = (lane >> 4) << 3;
    const uint32_t aHiB = sptr(sAhi), aLoB = sptr(sAlo);
    const uint32_t wHiB = sptr(sWhi), wLoB = sptr(sWlo);

    load_blk(0);
    store_blk(0);
    __syncthreads();

    for (int kb = 0; kb < NB; kb++) {
        if (kb + 1 < NB) load_blk((kb + 1) * 32);

#pragma unroll
        for (int ks = 0; ks < 32; ks += 16) {
            uint32_t ah[4][4], al[4][4], wh[4][2], wl[4][2];
#pragma unroll
            for (int i = 0; i < 4; i++) {
                uint32_t off = (uint32_t)((wm + i * 16 + lr15) * ASTR + ks + lk8) * 2;
                ldmx4(ah[i], aHiB + off);
                ldmx4(al[i], aLoB + off);
            }
#pragma unroll
            for (int p = 0; p < 2; p++) {
                uint32_t off = (uint32_t)((wn + p * 16 + lr15) * ASTR + ks + lk8) * 2;
                uint32_t r[4];
                ldmx4(r, wHiB + off);
                wh[2 * p][0] = r[0]; wh[2 * p][1] = r[2];
                wh[2 * p + 1][0] = r[1]; wh[2 * p + 1][1] = r[3];
                ldmx4(r, wLoB + off);
                wl[2 * p][0] = r[0]; wl[2 * p][1] = r[2];
                wl[2 * p + 1][0] = r[1]; wl[2 * p + 1][1] = r[3];
            }
#pragma unroll
            for (int i = 0; i < 4; i++)
#pragma unroll
                for (int j = 0; j < 4; j++) {
                    mma16816(c[i][j], ah[i], wh[j]);
                    mma16816(c[i][j], ah[i], wl[j]);
                    mma16816(c[i][j], al[i], wh[j]);
                }
        }
        __syncthreads();
        if (kb + 1 < NB) store_blk((kb + 1) * 32);
        __syncthreads();
    }

    // Epilogue: +bias, store fp32, accumulate GN stats (whole warp -> one group)
    float s = 0.0f, s2 = 0.0f;
#pragma unroll
    for (int i = 0; i < 4; i++) {
#pragma unroll
        for (int j = 0; j < 4; j++) {
            int row = m0 + wm + i * 16 + (lane >> 2);
            int col = n0 + wn + j * 8 + (lane & 3) * 2;
            float b0 = __ldg(bias + col), b1 = __ldg(bias + col + 1);
            float v0 = c[i][j][0] + b0, v1 = c[i][j][1] + b1;
            float v2 = c[i][j][2] + b0, v3 = c[i][j][3] + b1;
            *(float2*)&Co[(size_t)row * ON + col]       = make_float2(v0, v1);
            *(float2*)&Co[(size_t)(row + 8) * ON + col] = make_float2(v2, v3);
            s  += v0 + v1 + v2 + v3;
            s2 += v0 * v0 + v1 * v1 + v2 * v2 + v3 * v3;
        }
    }
#pragma unroll
    for (int off = 16; off >= 1; off >>= 1) {
        s  += __shfl_xor_sync(0xffffffffu, s,  off);
        s2 += __shfl_xor_sync(0xffffffffu, s2, off);
    }
    if (lane == 0) {
        int g = (n0 + wn) / (ON / 8);
        atomicAdd(&g_sum[STAGE * 64 + b * 8 + g], s);
        atomicAdd(&g_sqs[STAGE * 64 + b * 8 + g], s2);
    }
}

// ---------------------------------------------------------------------------
// Finalize GN stats -> per-(b,c) affine coefs: x*a + bb == gn(x)*gw+gb
// ---------------------------------------------------------------------------
template <int STAGE, int CCH>
__global__ void finalize_k(const float* __restrict__ gw, const float* __restrict__ gb) {
    int b = blockIdx.x, c = threadIdx.x;
    int g = c / (CCH / 8);
    float cnt  = (float)(CCH / 8) * (float)NP;
    float mean = g_sum[STAGE * 64 + b * 8 + g] / cnt;
    float var  = g_sqs[STAGE * 64 + b * 8 + g] / cnt - mean * mean;
    float rstd = rsqrtf(var + 1e-5f);
    float a  = rstd * gw[c];
    float bb = gb[c] - mean * a;
    if      (STAGE == 0) { g_cA0[b * CCH + c] = a; g_cB0[b * CCH + c] = bb; }
    else if (STAGE == 1) { g_cA1[b * CCH + c] = a; g_cB1[b * CCH + c] = bb; }
    else                 { g_cA2[b * CCH + c] = a; g_cB2[b * CCH + c] = bb; }
}

// ---------------------------------------------------------------------------
// Final: out[b,c,n] = gn2(h2)*(1+scale)+shift + silu(gn0(y1))  (with transpose)
// ---------------------------------------------------------------------------
__global__ void final_k(float* __restrict__ out) {
    __shared__ float t[32][33];
    int b  = blockIdx.z;
    int n0 = blockIdx.x * 32;
    int c0 = blockIdx.y * 32;
    int tx = threadIdx.x, ty = threadIdx.y;
#pragma unroll
    for (int i = 0; i < 4; i++) {
        int nl = ty + i * 8;
        size_t m = (size_t)b * NP + n0 + nl;
        int c = c0 + tx;
        float h2 = g_h2[m * C1 + c];
        float hn = h2 * g_cA2[b * C1 + c] + g_cB2[b * C1 + c];
        float y1 = g_y1[m * C1 + c];
        float idn = silu_f(y1 * g_cA0[b * C1 + c] + g_cB0[b * C1 + c]);
        float v = hn * (1.0f + g_scale[b * C1 + c]) + g_shift[b * C1 + c] + idn;
        t[nl][tx] = v;
    }
    __syncthreads();
#pragma unroll
    for (int i = 0; i < 4; i++) {
        int cl = ty + i * 8;
        out[((size_t)b * C1 + c0 + cl) * NP + n0 + tx] = t[tx][cl];
    }
}

// ---------------------------------------------------------------------------
// Launch
// ---------------------------------------------------------------------------
extern "C" void kernel_launch(void* const* d_in, const int* in_sizes, int n_in,
                              void* d_out, int out_size) {
    (void)in_sizes; (void)n_in; (void)out_size;
    const float* xyz1    = (const float*)d_in[0];
    const float* points1 = (const float*)d_in[1];
    const float* xyz2    = (const float*)d_in[2];
    const float* points2 = (const float*)d_in[3];
    const float* t_emb   = (const float*)d_in[4];
    const float* c_emb   = (const float*)d_in[5];
    const float* mlp_w   = (const float*)d_in[6];
    const float* mlp_b   = (const float*)d_in[7];
    const float* mlp_gw  = (const float*)d_in[8];
    const float* mlp_gb  = (const float*)d_in[9];
    const float* c1w     = (const float*)d_in[10];
    const float* c1b     = (const float*)d_in[11];
    const float* g1w     = (const float*)d_in[12];
    const float* g1b     = (const float*)d_in[13];
    const float* c2w     = (const float*)d_in[14];
    const float* c2b     = (const float*)d_in[15];
    const float* g2w     = (const float*)d_in[16];
    const float* g2b     = (const float*)d_in[17];
    const float* tw      = (const float*)d_in[18];
    const float* tb      = (const float*)d_in[19];
    const float* cw      = (const float*)d_in[20];
    const float* cb      = (const float*)d_in[21];
    float* out = (float*)d_out;

    zero_k<<<1, 256>>>();
    tr_p1_k<<<dim3(NP / 32, CSK / 32, BB), dim3(32, 8)>>>(points1);
    tr_p2_k<<<dim3(SP / 32, CIN / 32, BB), dim3(32, 8)>>>(points2);
    emb_k<<<512, 256>>>(t_emb, c_emb, tw, tb, cw, cb);
    knn_k<<<dim3(NP / 128, BB), 128>>>(xyz1, xyz2);

    gemm_k<C0, C1, 0><<<dim3(MTOT / 128, C1 / 128), 256>>>(mlp_w, mlp_b);
    finalize_k<0, C1><<<BB, C1>>>(mlp_gw, mlp_gb);

    gemm_k<C1, CE, 1><<<dim3(MTOT / 128, CE / 128), 256>>>(c1w, c1b);
    finalize_k<1, CE><<<BB, CE>>>(g1w, g1b);

    gemm_k<CE, C1, 2><<<dim3(MTOT / 128, C1 / 128), 256>>>(c2w, c2b);
    finalize_k<2, C1><<<BB, C1>>>(g2w, g2b);

    final_k<<<dim3(NP / 32, C1 / 32, BB), dim3(32, 8)>>>(out);
}

// round 5
// speedup vs baseline: 1.3712x; 1.0059x over previous
#include <cuda_runtime.h>
#include <cuda_bf16.h>
#include <cstdint>

// ---------------------------------------------------------------------------
// Problem constants
// ---------------------------------------------------------------------------
constexpr int BB   = 8;
constexpr int NP   = 8192;
constexpr int SP   = 2048;
constexpr int CIN  = 256;     // points2 channels
constexpr int CSK  = 128;     // points1 channels (skip)
constexpr int C0   = 384;     // IN+SKIP
constexpr int C1   = 256;     // OUT
constexpr int CE   = 1024;    // OUT*EXP
constexpr int MTOT = BB * NP; // 65536 rows

// ---------------------------------------------------------------------------
// Scratch (device globals; no dynamic allocation allowed)
// ---------------------------------------------------------------------------
static __device__ float g_A1 [MTOT * C0];      // new_points, row-major [m, 384]
static __device__ float g_p2t[BB * SP * CIN];  // points2 transposed [b, s, c]
static __device__ float g_y1 [MTOT * C1];      // conv0 out (pre-GN)
static __device__ float g_h1 [MTOT * CE];      // conv1 out (pre-GN)
static __device__ float g_h2 [MTOT * C1];      // conv2 out (pre-GN)
static __device__ float g_sum[3 * 64];         // per-stage (b,g) sums
static __device__ float g_sqs[3 * 64];         // per-stage (b,g) sum-squares
static __device__ float g_cA0[BB * C1], g_cB0[BB * C1];
static __device__ float g_cA1[BB * CE], g_cB1[BB * CE];
static __device__ float g_cA2[BB * C1], g_cB2[BB * C1];
static __device__ float g_scale[BB * C1], g_shift[BB * C1];

__device__ __forceinline__ float silu_f(float x) {
    return __fdividef(x, 1.0f + __expf(-x));
}

// ---------------------------------------------------------------------------
// MMA helpers (sm_80-style bf16 tensor core path, valid on sm_100a)
// ---------------------------------------------------------------------------
__device__ __forceinline__ uint32_t sptr(const void* p) {
    return (uint32_t)__cvta_generic_to_shared(p);
}
__device__ __forceinline__ void ldmx4(uint32_t* r, uint32_t addr) {
    asm volatile("ldmatrix.sync.aligned.m8n8.x4.shared.b16 {%0,%1,%2,%3}, [%4];\n"
                 : "=r"(r[0]), "=r"(r[1]), "=r"(r[2]), "=r"(r[3]) : "r"(addr));
}
__device__ __forceinline__ void mma16816(float* c, const uint32_t* a, const uint32_t* b) {
    asm volatile(
        "mma.sync.aligned.m16n8k16.row.col.f32.bf16.bf16.f32 "
        "{%0,%1,%2,%3}, {%4,%5,%6,%7}, {%8,%9}, {%0,%1,%2,%3};\n"
        : "+f"(c[0]), "+f"(c[1]), "+f"(c[2]), "+f"(c[3])
        : "r"(a[0]), "r"(a[1]), "r"(a[2]), "r"(a[3]), "r"(b[0]), "r"(b[1]));
}

// ---------------------------------------------------------------------------
// Zero the stats accumulators (must happen every launch)
// ---------------------------------------------------------------------------
__global__ void zero_k() {
    int i = threadIdx.x;
    if (i < 192) { g_sum[i] = 0.0f; g_sqs[i] = 0.0f; }
}

// ---------------------------------------------------------------------------
// Transpose points1 [B,128,N] -> g_A1 columns [0,128)   (row-major [m,384])
// ---------------------------------------------------------------------------
__global__ void tr_p1_k(const float* __restrict__ src) {
    __shared__ float t[32][33];
    int b  = blockIdx.z;
    int n0 = blockIdx.x * 32;
    int c0 = blockIdx.y * 32;
    int tx = threadIdx.x, ty = threadIdx.y;
#pragma unroll
    for (int i = 0; i < 4; i++) {
        int cl = ty + i * 8;
        t[cl][tx] = src[((size_t)b * CSK + (c0 + cl)) * NP + n0 + tx];
    }
    __syncthreads();
#pragma unroll
    for (int i = 0; i < 4; i++) {
        int nl = ty + i * 8;
        g_A1[((size_t)b * NP + (n0 + nl)) * C0 + c0 + tx] = t[tx][nl];
    }
}

// ---------------------------------------------------------------------------
// Transpose points2 [B,256,S] -> g_p2t [b, s, c]
// ---------------------------------------------------------------------------
__global__ void tr_p2_k(const float* __restrict__ src) {
    __shared__ float t[32][33];
    int b  = blockIdx.z;
    int s0 = blockIdx.x * 32;
    int c0 = blockIdx.y * 32;
    int tx = threadIdx.x, ty = threadIdx.y;
#pragma unroll
    for (int i = 0; i < 4; i++) {
        int cl = ty + i * 8;
        t[cl][tx] = src[((size_t)b * CIN + (c0 + cl)) * SP + s0 + tx];
    }
    __syncthreads();
#pragma unroll
    for (int i = 0; i < 4; i++) {
        int sl = ty + i * 8;
        g_p2t[((size_t)b * SP + (s0 + sl)) * CIN + c0 + tx] = t[tx][sl];
    }
}

// ---------------------------------------------------------------------------
// Embedding modulation: one warp per (b, output-row j) -> full-chip parallel
// ---------------------------------------------------------------------------
__global__ void emb_k(const float* __restrict__ t_emb, const float* __restrict__ c_emb,
                      const float* __restrict__ tw, const float* __restrict__ tb,
                      const float* __restrict__ cw, const float* __restrict__ cb) {
    int gw   = (blockIdx.x * blockDim.x + threadIdx.x) >> 5;  // 0..4095
    int lane = threadIdx.x & 31;
    int b = gw >> 9;        // 512 outputs per batch
    int j = gw & 511;       // 0..511
    const float* twr = tw + (size_t)j * C1;
    const float* cwr = cw + (size_t)j * C1;
    const float* te  = t_emb + b * C1;
    const float* ce  = c_emb + b * C1;
    int k0 = lane * 8;
    float4 a0 = *(const float4*)(twr + k0);
    float4 a1 = *(const float4*)(twr + k0 + 4);
    float4 b0 = *(const float4*)(cwr + k0);
    float4 b1 = *(const float4*)(cwr + k0 + 4);
    float4 t0 = *(const float4*)(te + k0);
    float4 t1 = *(const float4*)(te + k0 + 4);
    float4 c0 = *(const float4*)(ce + k0);
    float4 c1 = *(const float4*)(ce + k0 + 4);
    float s = a0.x * t0.x + a0.y * t0.y + a0.z * t0.z + a0.w * t0.w
            + a1.x * t1.x + a1.y * t1.y + a1.z * t1.z + a1.w * t1.w
            + b0.x * c0.x + b0.y * c0.y + b0.z * c0.z + b0.w * c0.w
            + b1.x * c1.x + b1.y * c1.y + b1.z * c1.z + b1.w * c1.w;
#pragma unroll
    for (int off = 16; off >= 1; off >>= 1) s += __shfl_xor_sync(0xffffffffu, s, off);
    if (lane == 0) {
        s += tb[j] + cb[j];
        if (j < C1) g_scale[b * C1 + j] = s;
        else        g_shift[b * C1 + (j - C1)] = s;
    }
}

// ---------------------------------------------------------------------------
// 3-NN + inverse-distance-weighted interpolation. Writes g_A1 cols [128,384).
// ---------------------------------------------------------------------------
__global__ void knn_k(const float* __restrict__ xyz1, const float* __restrict__ xyz2) {
    __shared__ float4 ref[SP];  // (x,y,z,|p|^2) per ref point : 32 KB
    int b = blockIdx.y;
    int n = blockIdx.x * 128 + threadIdx.x;
    for (int s = threadIdx.x; s < SP; s += 128) {
        float x = xyz2[((size_t)b * 3 + 0) * SP + s];
        float y = xyz2[((size_t)b * 3 + 1) * SP + s];
        float z = xyz2[((size_t)b * 3 + 2) * SP + s];
        ref[s] = make_float4(x, y, z, x * x + y * y + z * z);
    }
    __syncthreads();

    float px = xyz1[((size_t)b * 3 + 0) * NP + n];
    float py = xyz1[((size_t)b * 3 + 1) * NP + n];
    float pz = xyz1[((size_t)b * 3 + 2) * NP + n];
    float n1 = px * px + py * py + pz * pz;

    float d0 = 3.4e38f, d1 = 3.4e38f, d2 = 3.4e38f;
    int   i0 = 0, i1 = 0, i2 = 0;
    for (int s = 0; s < SP; s++) {
        float4 r = ref[s];
        float dot = px * r.x + py * r.y + pz * r.z;
        float d = (-2.0f * dot + n1) + r.w;   // same formula as reference
        if (d < d2) {
            if (d < d1) {
                d2 = d1; i2 = i1;
                if (d < d0) { d1 = d0; i1 = i0; d0 = d; i0 = s; }
                else        { d1 = d;  i1 = s; }
            } else { d2 = d; i2 = s; }
        }
    }

    float r0 = 1.0f / (d0 + 1e-8f);
    float r1 = 1.0f / (d1 + 1e-8f);
    float r2 = 1.0f / (d2 + 1e-8f);
    float rs = r0 + r1 + r2;
    float w0 = r0 / rs, w1 = r1 / rs, w2 = r2 / rs;

    const float4* p0 = (const float4*)&g_p2t[((size_t)b * SP + i0) * CIN];
    const float4* p1 = (const float4*)&g_p2t[((size_t)b * SP + i1) * CIN];
    const float4* p2 = (const float4*)&g_p2t[((size_t)b * SP + i2) * CIN];
    float4* dst = (float4*)&g_A1[((size_t)b * NP + n) * C0 + CSK];
#pragma unroll 4
    for (int c = 0; c < CIN / 4; c++) {
        float4 a = p0[c], bq = p1[c], cq = p2[c];
        float4 o;
        o.x = a.x * w0 + bq.x * w1 + cq.x * w2;
        o.y = a.y * w0 + bq.y * w1 + cq.y * w2;
        o.z = a.z * w0 + bq.z * w1 + cq.z * w2;
        o.w = a.w * w0 + bq.w * w1 + cq.w * w2;
        dst[c] = o;
    }
}

// ---------------------------------------------------------------------------
// Tensor-core GEMM with fp32 emulation via bf16 hi/lo split (3 products).
//   C[m,o] = sum_k f(A[m,k]) * W[o,k] + bias[o]
//   STAGE 0: A = g_A1 (raw)      -> g_y1, stats[0]
//   STAGE 1: A = silu(gn0(g_y1)) -> g_h1, stats[1]
//   STAGE 2: A = silu(gn1(g_h1)) -> g_h2, stats[2]
// BM=BN=128, BK=32, 256 threads (8 warps: 2m x 4n, 64x32 warp tile).
// ---------------------------------------------------------------------------
constexpr int ASTR = 40;  // smem row stride (bf16): 8 rows x 80B hit distinct banks

template <int K, int ON, int STAGE>
__global__ __launch_bounds__(256) void gemm_k(const float* __restrict__ W,
                                              const float* __restrict__ bias) {
    constexpr bool TRANSF = (STAGE > 0);
    constexpr int NB = K / 32;

    __shared__ __nv_bfloat16 sAhi[128][ASTR], sAlo[128][ASTR];
    __shared__ __nv_bfloat16 sWhi[128][ASTR], sWlo[128][ASTR];

    const float* A  = (STAGE == 0) ? g_A1 : (STAGE == 1 ? g_y1 : g_h1);
    float*       Co = (STAGE == 0) ? g_y1 : (STAGE == 1 ? g_h1 : g_h2);

    const int tid  = threadIdx.x;
    const int m0   = blockIdx.x * 128;
    const int n0   = blockIdx.y * 128;
    const int b    = m0 >> 13;  // NP = 8192
    const int lane = tid & 31;
    const int warp = tid >> 5;
    const int wm   = (warp & 1) * 64;   // warp m-offset
    const int wn   = (warp >> 1) * 32;  // warp n-offset

    const float* cA = nullptr;
    const float* cB = nullptr;
    if (TRANSF) {
        if (STAGE == 1) { cA = g_cA0 + b * K; cB = g_cB0 + b * K; }
        else            { cA = g_cA1 + b * K; cB = g_cB1 + b * K; }
    }

    // global->reg staging: each thread owns (row = tid>>1, khalf = (tid&1)*16)
    const int grow = tid >> 1;
    const int kh   = (tid & 1) * 16;

    float4 pa[4], pw[4];
    auto load_blk = [&](int k0) {
        const float4* ap = (const float4*)(A + (size_t)(m0 + grow) * K + k0 + kh);
        const float4* wp = (const float4*)(W + (size_t)(n0 + grow) * K + k0 + kh);
#pragma unroll
        for (int q = 0; q < 4; q++) { pa[q] = ap[q]; pw[q] = wp[q]; }
    };
    auto store_blk = [&](int k0) {
#pragma unroll
        for (int q = 0; q < 4; q++) {
            float4 v = pa[q];
            if (TRANSF) {
                int kk = k0 + kh + q * 4;
                v.x = silu_f(v.x * __ldg(cA + kk + 0) + __ldg(cB + kk + 0));
                v.y = silu_f(v.y * __ldg(cA + kk + 1) + __ldg(cB + kk + 1));
                v.z = silu_f(v.z * __ldg(cA + kk + 2) + __ldg(cB + kk + 2));
                v.w = silu_f(v.w * __ldg(cA + kk + 3) + __ldg(cB + kk + 3));
            }
            __nv_bfloat16 hx = __float2bfloat16(v.x), hy = __float2bfloat16(v.y);
            __nv_bfloat16 hz = __float2bfloat16(v.z), hw = __float2bfloat16(v.w);
            __nv_bfloat16 lx = __float2bfloat16(v.x - __bfloat162float(hx));
            __nv_bfloat16 ly = __float2bfloat16(v.y - __bfloat162float(hy));
            __nv_bfloat16 lz = __float2bfloat16(v.z - __bfloat162float(hz));
            __nv_bfloat16 lw = __float2bfloat16(v.w - __bfloat162float(hw));
            int c4 = kh + q * 4;
            *(__nv_bfloat162*)&sAhi[grow][c4]     = __halves2bfloat162(hx, hy);
            *(__nv_bfloat162*)&sAhi[grow][c4 + 2] = __halves2bfloat162(hz, hw);
            *(__nv_bfloat162*)&sAlo[grow][c4]     = __halves2bfloat162(lx, ly);
            *(__nv_bfloat162*)&sAlo[grow][c4 + 2] = __halves2bfloat162(lz, lw);

            float4 u = pw[q];
            __nv_bfloat16 ux = __float2bfloat16(u.x), uy = __float2bfloat16(u.y);
            __nv_bfloat16 uz = __float2bfloat16(u.z), uw = __float2bfloat16(u.w);
            __nv_bfloat16 vx = __float2bfloat16(u.x - __bfloat162float(ux));
            __nv_bfloat16 vy = __float2bfloat16(u.y - __bfloat162float(uy));
            __nv_bfloat16 vz = __float2bfloat16(u.z - __bfloat162float(uz));
            __nv_bfloat16 vw = __float2bfloat16(u.w - __bfloat162float(uw));
            *(__nv_bfloat162*)&sWhi[grow][c4]     = __halves2bfloat162(ux, uy);
            *(__nv_bfloat162*)&sWhi[grow][c4 + 2] = __halves2bfloat162(uz, uw);
            *(__nv_bfloat162*)&sWlo[grow][c4]     = __halves2bfloat162(vx, vy);
            *(__nv_bfloat162*)&sWlo[grow][c4 + 2] = __halves2bfloat162(vz, vw);
        }
    };

    float c[4][4][4];
#pragma unroll
    for (int i = 0; i < 4; i++)
#pragma unroll
        for (int j = 0; j < 4; j++)
#pragma unroll
            for (int r = 0; r < 4; r++) c[i][j][r] = 0.0f;

    // ldmatrix per-lane addressing (row = lane&15, k-half = (lane>>4)*8)
    const int lr15 = lane & 15;
    const int lk8  = (lane >> 4) << 3;
    const uint32_t aHiB = sptr(sAhi), aLoB = sptr(sAlo);
    const uint32_t wHiB = sptr(sWhi), wLoB = sptr(sWlo);

    load_blk(0);
    store_blk(0);
    __syncthreads();

    for (int kb = 0; kb < NB; kb++) {
        if (kb + 1 < NB) load_blk((kb + 1) * 32);

#pragma unroll
        for (int ks = 0; ks < 32; ks += 16) {
            uint32_t ah[4][4], al[4][4], wh[4][2], wl[4][2];
#pragma unroll
            for (int i = 0; i < 4; i++) {
                uint32_t off = (uint32_t)((wm + i * 16 + lr15) * ASTR + ks + lk8) * 2;
                ldmx4(ah[i], aHiB + off);
                ldmx4(al[i], aLoB + off);
            }
#pragma unroll
            for (int p = 0; p < 2; p++) {
                uint32_t off = (uint32_t)((wn + p * 16 + lr15) * ASTR + ks + lk8) * 2;
                uint32_t r[4];
                ldmx4(r, wHiB + off);
                wh[2 * p][0] = r[0]; wh[2 * p][1] = r[2];
                wh[2 * p + 1][0] = r[1]; wh[2 * p + 1][1] = r[3];
                ldmx4(r, wLoB + off);
                wl[2 * p][0] = r[0]; wl[2 * p][1] = r[2];
                wl[2 * p + 1][0] = r[1]; wl[2 * p + 1][1] = r[3];
            }
#pragma unroll
            for (int i = 0; i < 4; i++)
#pragma unroll
                for (int j = 0; j < 4; j++) {
                    mma16816(c[i][j], ah[i], wh[j]);
                    mma16816(c[i][j], ah[i], wl[j]);
                    mma16816(c[i][j], al[i], wh[j]);
                }
        }
        __syncthreads();
        if (kb + 1 < NB) store_blk((kb + 1) * 32);
        __syncthreads();
    }

    // Epilogue: +bias, store fp32, accumulate GN stats (whole warp -> one group)
    float s = 0.0f, s2 = 0.0f;
#pragma unroll
    for (int i = 0; i < 4; i++) {
#pragma unroll
        for (int j = 0; j < 4; j++) {
            int row = m0 + wm + i * 16 + (lane >> 2);
            int col = n0 + wn + j * 8 + (lane & 3) * 2;
            float b0 = __ldg(bias + col), b1 = __ldg(bias + col + 1);
            float v0 = c[i][j][0] + b0, v1 = c[i][j][1] + b1;
            float v2 = c[i][j][2] + b0, v3 = c[i][j][3] + b1;
            *(float2*)&Co[(size_t)row * ON + col]       = make_float2(v0, v1);
            *(float2*)&Co[(size_t)(row + 8) * ON + col] = make_float2(v2, v3);
            s  += v0 + v1 + v2 + v3;
            s2 += v0 * v0 + v1 * v1 + v2 * v2 + v3 * v3;
        }
    }
#pragma unroll
    for (int off = 16; off >= 1; off >>= 1) {
        s  += __shfl_xor_sync(0xffffffffu, s,  off);
        s2 += __shfl_xor_sync(0xffffffffu, s2, off);
    }
    if (lane == 0) {
        int g = (n0 + wn) / (ON / 8);
        atomicAdd(&g_sum[STAGE * 64 + b * 8 + g], s);
        atomicAdd(&g_sqs[STAGE * 64 + b * 8 + g], s2);
    }
}

// ---------------------------------------------------------------------------
// Finalize GN stats -> per-(b,c) affine coefs: x*a + bb == gn(x)*gw+gb
// ---------------------------------------------------------------------------
template <int STAGE, int CCH>
__global__ void finalize_k(const float* __restrict__ gw, const float* __restrict__ gb) {
    int b = blockIdx.x, c = threadIdx.x;
    int g = c / (CCH / 8);
    float cnt  = (float)(CCH / 8) * (float)NP;
    float mean = g_sum[STAGE * 64 + b * 8 + g] / cnt;
    float var  = g_sqs[STAGE * 64 + b * 8 + g] / cnt - mean * mean;
    float rstd = rsqrtf(var + 1e-5f);
    float a  = rstd * gw[c];
    float bb = gb[c] - mean * a;
    if      (STAGE == 0) { g_cA0[b * CCH + c] = a; g_cB0[b * CCH + c] = bb; }
    else if (STAGE == 1) { g_cA1[b * CCH + c] = a; g_cB1[b * CCH + c] = bb; }
    else                 { g_cA2[b * CCH + c] = a; g_cB2[b * CCH + c] = bb; }
}

// ---------------------------------------------------------------------------
// Final: out[b,c,n] = gn2(h2)*(1+scale)+shift + silu(gn0(y1))  (with transpose)
// ---------------------------------------------------------------------------
__global__ void final_k(float* __restrict__ out) {
    __shared__ float t[32][33];
    int b  = blockIdx.z;
    int n0 = blockIdx.x * 32;
    int c0 = blockIdx.y * 32;
    int tx = threadIdx.x, ty = threadIdx.y;
#pragma unroll
    for (int i = 0; i < 4; i++) {
        int nl = ty + i * 8;
        size_t m = (size_t)b * NP + n0 + nl;
        int c = c0 + tx;
        float h2 = g_h2[m * C1 + c];
        float hn = h2 * g_cA2[b * C1 + c] + g_cB2[b * C1 + c];
        float y1 = g_y1[m * C1 + c];
        float idn = silu_f(y1 * g_cA0[b * C1 + c] + g_cB0[b * C1 + c]);
        float v = hn * (1.0f + g_scale[b * C1 + c]) + g_shift[b * C1 + c] + idn;
        t[nl][tx] = v;
    }
    __syncthreads();
#pragma unroll
    for (int i = 0; i < 4; i++) {
        int cl = ty + i * 8;
        out[((size_t)b * C1 + c0 + cl) * NP + n0 + tx] = t[tx][cl];
    }
}

// ---------------------------------------------------------------------------
// Launch
// ---------------------------------------------------------------------------
extern "C" void kernel_launch(void* const* d_in, const int* in_sizes, int n_in,
                              void* d_out, int out_size) {
    (void)in_sizes; (void)n_in; (void)out_size;
    const float* xyz1    = (const float*)d_in[0];
    const float* points1 = (const float*)d_in[1];
    const float* xyz2    = (const float*)d_in[2];
    const float* points2 = (const float*)d_in[3];
    const float* t_emb   = (const float*)d_in[4];
    const float* c_emb   = (const float*)d_in[5];
    const float* mlp_w   = (const float*)d_in[6];
    const float* mlp_b   = (const float*)d_in[7];
    const float* mlp_gw  = (const float*)d_in[8];
    const float* mlp_gb  = (const float*)d_in[9];
    const float* c1w     = (const float*)d_in[10];
    const float* c1b     = (const float*)d_in[11];
    const float* g1w     = (const float*)d_in[12];
    const float* g1b     = (const float*)d_in[13];
    const float* c2w     = (const float*)d_in[14];
    const float* c2b     = (const float*)d_in[15];
    const float* g2w     = (const float*)d_in[16];
    const float* g2b     = (const float*)d_in[17];
    const float* tw      = (const float*)d_in[18];
    const float* tb      = (const float*)d_in[19];
    const float* cw      = (const float*)d_in[20];
    const float* cb      = (const float*)d_in[21];
    float* out = (float*)d_out;

    zero_k<<<1, 256>>>();
    tr_p1_k<<<dim3(NP / 32, CSK / 32, BB), dim3(32, 8)>>>(points1);
    tr_p2_k<<<dim3(SP / 32, CIN / 32, BB), dim3(32, 8)>>>(points2);
    emb_k<<<512, 256>>>(t_emb, c_emb, tw, tb, cw, cb);
    knn_k<<<dim3(NP / 128, BB), 128>>>(xyz1, xyz2);

    gemm_k<C0, C1, 0><<<dim3(MTOT / 128, C1 / 128), 256>>>(mlp_w, mlp_b);
    finalize_k<0, C1><<<BB, C1>>>(mlp_gw, mlp_gb);

    gemm_k<C1, CE, 1><<<dim3(MTOT / 128, CE / 128), 256>>>(c1w, c1b);
    finalize_k<1, CE><<<BB, CE>>>(g1w, g1b);

    gemm_k<CE, C1, 2><<<dim3(MTOT / 128, C1 / 128), 256>>>(c2w, c2b);
    finalize_k<2, C1><<<BB, C1>>>(g2w, g2b);

    final_k<<<dim3(NP / 32, C1 / 32, BB), dim3(32, 8)>>>(out);
}

// round 10
// speedup vs baseline: 1.5120x; 1.1027x over previous
#include <cuda_runtime.h>
#include <cuda_bf16.h>
#include <cstdint>

// ---------------------------------------------------------------------------
// Problem constants
// ---------------------------------------------------------------------------
constexpr int BB   = 8;
constexpr int NP   = 8192;
constexpr int SP   = 2048;
constexpr int CIN  = 256;
constexpr int CSK  = 128;
constexpr int C0   = 384;     // IN+SKIP
constexpr int C1   = 256;     // OUT
constexpr int CE   = 1024;    // OUT*EXP
constexpr int MTOT = BB * NP; // 65536 rows

// ---------------------------------------------------------------------------
// Scratch (device globals; no dynamic allocation allowed)
// ---------------------------------------------------------------------------
static __device__ __nv_bfloat16 g_A0h[MTOT * C0], g_A0l[MTOT * C0]; // stage0 A planes
static __device__ __nv_bfloat16 g_X1h[MTOT * C1], g_X1l[MTOT * C1]; // stage1 A planes
static __device__ __nv_bfloat16 g_X2h[MTOT * CE], g_X2l[MTOT * CE]; // stage2 A planes
static __device__ __nv_bfloat16 g_W0h[C1 * C0], g_W0l[C1 * C0];
static __device__ __nv_bfloat16 g_W1h[CE * C1], g_W1l[CE * C1];
static __device__ __nv_bfloat16 g_W2h[C1 * CE], g_W2l[C1 * CE];
static __device__ float g_p2t[BB * SP * CIN];  // points2 transposed [b, s, c]
static __device__ float g_y1 [MTOT * C1];      // conv0 out (pre-GN)
static __device__ float g_h1 [MTOT * CE];      // conv1 out (pre-GN)
static __device__ float g_h2 [MTOT * C1];      // conv2 out (pre-GN)
static __device__ float g_sum[3 * 64];
static __device__ float g_sqs[3 * 64];
static __device__ float g_cA0[BB * C1], g_cB0[BB * C1];
static __device__ float g_cA1[BB * CE], g_cB1[BB * CE];
static __device__ float g_cA2[BB * C1], g_cB2[BB * C1];
static __device__ float g_scale[BB * C1], g_shift[BB * C1];

__device__ __forceinline__ float silu_f(float x) {
    return __fdividef(x, 1.0f + __expf(-x));
}
__device__ __forceinline__ void split2(float x, __nv_bfloat16& h, __nv_bfloat16& l) {
    h = __float2bfloat16(x);
    l = __float2bfloat16(x - __bfloat162float(h));
}

// ---------------------------------------------------------------------------
// MMA helpers (legacy bf16 tensor-core path; available on plain sm_100 target)
// ---------------------------------------------------------------------------
__device__ __forceinline__ uint32_t sptr(const void* p) {
    return (uint32_t)__cvta_generic_to_shared(p);
}
__device__ __forceinline__ void ldmx4(uint32_t* r, uint32_t addr) {
    asm volatile("ldmatrix.sync.aligned.m8n8.x4.shared.b16 {%0,%1,%2,%3}, [%4];\n"
                 : "=r"(r[0]), "=r"(r[1]), "=r"(r[2]), "=r"(r[3]) : "r"(addr));
}
__device__ __forceinline__ void mma16816(float* c, const uint32_t* a, const uint32_t* b) {
    asm volatile(
        "mma.sync.aligned.m16n8k16.row.col.f32.bf16.bf16.f32 "
        "{%0,%1,%2,%3}, {%4,%5,%6,%7}, {%8,%9}, {%0,%1,%2,%3};\n"
        : "+f"(c[0]), "+f"(c[1]), "+f"(c[2]), "+f"(c[3])
        : "r"(a[0]), "r"(a[1]), "r"(a[2]), "r"(a[3]), "r"(b[0]), "r"(b[1]));
}

// ---------------------------------------------------------------------------
// Zero the stats accumulators
// ---------------------------------------------------------------------------
__global__ void zero_k() {
    int i = threadIdx.x;
    if (i < 192) { g_sum[i] = 0.0f; g_sqs[i] = 0.0f; }
}

// ---------------------------------------------------------------------------
// Weight split: fp32 -> bf16 hi/lo planes.
// ---------------------------------------------------------------------------
template <int WS>
__global__ void wsplit_k(const float* __restrict__ w, int n8) {
    int i = blockIdx.x * 256 + threadIdx.x;
    if (i >= n8) return;
    __nv_bfloat16* hi = (WS == 0) ? g_W0h : (WS == 1 ? g_W1h : g_W2h);
    __nv_bfloat16* lo = (WS == 0) ? g_W0l : (WS == 1 ? g_W1l : g_W2l);
    const float4* wp = (const float4*)w + 2 * i;
    float4 a = wp[0], b = wp[1];
    __nv_bfloat16 h[8], l[8];
    split2(a.x, h[0], l[0]); split2(a.y, h[1], l[1]);
    split2(a.z, h[2], l[2]); split2(a.w, h[3], l[3]);
    split2(b.x, h[4], l[4]); split2(b.y, h[5], l[5]);
    split2(b.z, h[6], l[6]); split2(b.w, h[7], l[7]);
    *(uint4*)(hi + (size_t)i * 8) = *(uint4*)h;
    *(uint4*)(lo + (size_t)i * 8) = *(uint4*)l;
}

// ---------------------------------------------------------------------------
// Activation split: x -> silu(x*cA + cB) -> bf16 hi/lo planes (8 elems/thread)
// ---------------------------------------------------------------------------
template <int STAGE>
__global__ void asplit_k() {
    constexpr int C = (STAGE == 1) ? C1 : CE;
    const float* X  = (STAGE == 1) ? g_y1  : g_h1;
    const float* cA = (STAGE == 1) ? g_cA0 : g_cA1;
    const float* cB = (STAGE == 1) ? g_cB0 : g_cB1;
    __nv_bfloat16* oh = (STAGE == 1) ? g_X1h : g_X2h;
    __nv_bfloat16* ol = (STAGE == 1) ? g_X1l : g_X2l;

    size_t i = (size_t)blockIdx.x * 256 + threadIdx.x;   // per 8 elements
    int m  = (int)(i / (C / 8));
    int c0 = (int)(i % (C / 8)) * 8;
    int b  = m >> 13;
    const float4* xp = (const float4*)(X + (size_t)m * C + c0);
    float4 x0 = xp[0], x1 = xp[1];
    const float* a = cA + b * C + c0;
    const float* s = cB + b * C + c0;
    float v[8];
    v[0] = silu_f(x0.x * a[0] + s[0]); v[1] = silu_f(x0.y * a[1] + s[1]);
    v[2] = silu_f(x0.z * a[2] + s[2]); v[3] = silu_f(x0.w * a[3] + s[3]);
    v[4] = silu_f(x1.x * a[4] + s[4]); v[5] = silu_f(x1.y * a[5] + s[5]);
    v[6] = silu_f(x1.z * a[6] + s[6]); v[7] = silu_f(x1.w * a[7] + s[7]);
    __nv_bfloat16 h[8], l[8];
#pragma unroll
    for (int j = 0; j < 8; j++) split2(v[j], h[j], l[j]);
    *(uint4*)(oh + (size_t)m * C + c0) = *(uint4*)h;
    *(uint4*)(ol + (size_t)m * C + c0) = *(uint4*)l;
}

// ---------------------------------------------------------------------------
// Transpose points1 [B,128,N] -> stage0 A planes, columns [0,128)
// ---------------------------------------------------------------------------
__global__ void tr_p1_k(const float* __restrict__ src) {
    __shared__ float t[32][33];
    int b  = blockIdx.z;
    int n0 = blockIdx.x * 32;
    int c0 = blockIdx.y * 32;
    int tx = threadIdx.x, ty = threadIdx.y;
#pragma unroll
    for (int i = 0; i < 4; i++) {
        int cl = ty + i * 8;
        t[cl][tx] = src[((size_t)b * CSK + (c0 + cl)) * NP + n0 + tx];
    }
    __syncthreads();
#pragma unroll
    for (int i = 0; i < 4; i++) {
        int nl = ty + i * 8;
        size_t m = (size_t)b * NP + n0 + nl;
        __nv_bfloat16 h, l;
        split2(t[tx][nl], h, l);
        g_A0h[m * C0 + c0 + tx] = h;
        g_A0l[m * C0 + c0 + tx] = l;
    }
}

// ---------------------------------------------------------------------------
// Transpose points2 [B,256,S] -> g_p2t [b, s, c]
// ---------------------------------------------------------------------------
__global__ void tr_p2_k(const float* __restrict__ src) {
    __shared__ float t[32][33];
    int b  = blockIdx.z;
    int s0 = blockIdx.x * 32;
    int c0 = blockIdx.y * 32;
    int tx = threadIdx.x, ty = threadIdx.y;
#pragma unroll
    for (int i = 0; i < 4; i++) {
        int cl = ty + i * 8;
        t[cl][tx] = src[((size_t)b * CIN + (c0 + cl)) * SP + s0 + tx];
    }
    __syncthreads();
#pragma unroll
    for (int i = 0; i < 4; i++) {
        int sl = ty + i * 8;
        g_p2t[((size_t)b * SP + (s0 + sl)) * CIN + c0 + tx] = t[tx][sl];
    }
}

// ---------------------------------------------------------------------------
// Embedding modulation: one warp per (b, output-row j)
// ---------------------------------------------------------------------------
__global__ void emb_k(const float* __restrict__ t_emb, const float* __restrict__ c_emb,
                      const float* __restrict__ tw, const float* __restrict__ tb,
                      const float* __restrict__ cw, const float* __restrict__ cb) {
    int gw   = (blockIdx.x * blockDim.x + threadIdx.x) >> 5;
    int lane = threadIdx.x & 31;
    int b = gw >> 9;
    int j = gw & 511;
    const float* twr = tw + (size_t)j * C1;
    const float* cwr = cw + (size_t)j * C1;
    const float* te  = t_emb + b * C1;
    const float* ce  = c_emb + b * C1;
    int k0 = lane * 8;
    float4 a0 = *(const float4*)(twr + k0);
    float4 a1 = *(const float4*)(twr + k0 + 4);
    float4 b0 = *(const float4*)(cwr + k0);
    float4 b1 = *(const float4*)(cwr + k0 + 4);
    float4 t0 = *(const float4*)(te + k0);
    float4 t1 = *(const float4*)(te + k0 + 4);
    float4 c0 = *(const float4*)(ce + k0);
    float4 c1 = *(const float4*)(ce + k0 + 4);
    float s = a0.x * t0.x + a0.y * t0.y + a0.z * t0.z + a0.w * t0.w
            + a1.x * t1.x + a1.y * t1.y + a1.z * t1.z + a1.w * t1.w
            + b0.x * c0.x + b0.y * c0.y + b0.z * c0.z + b0.w * c0.w
            + b1.x * c1.x + b1.y * c1.y + b1.z * c1.z + b1.w * c1.w;
#pragma unroll
    for (int off = 16; off >= 1; off >>= 1) s += __shfl_xor_sync(0xffffffffu, s, off);
    if (lane == 0) {
        s += tb[j] + cb[j];
        if (j < C1) g_scale[b * C1 + j] = s;
        else        g_shift[b * C1 + (j - C1)] = s;
    }
}

// ---------------------------------------------------------------------------
// 3-NN + inverse-distance interpolation -> stage0 A planes cols [128,384)
// ---------------------------------------------------------------------------
__global__ void knn_k(const float* __restrict__ xyz1, const float* __restrict__ xyz2) {
    __shared__ float4 ref[SP];
    int b = blockIdx.y;
    int n = blockIdx.x * 128 + threadIdx.x;
    for (int s = threadIdx.x; s < SP; s += 128) {
        float x = xyz2[((size_t)b * 3 + 0) * SP + s];
        float y = xyz2[((size_t)b * 3 + 1) * SP + s];
        float z = xyz2[((size_t)b * 3 + 2) * SP + s];
        ref[s] = make_float4(x, y, z, x * x + y * y + z * z);
    }
    __syncthreads();

    float px = xyz1[((size_t)b * 3 + 0) * NP + n];
    float py = xyz1[((size_t)b * 3 + 1) * NP + n];
    float pz = xyz1[((size_t)b * 3 + 2) * NP + n];
    float n1 = px * px + py * py + pz * pz;

    float d0 = 3.4e38f, d1 = 3.4e38f, d2 = 3.4e38f;
    int   i0 = 0, i1 = 0, i2 = 0;
    for (int s = 0; s < SP; s++) {
        float4 r = ref[s];
        float dot = px * r.x + py * r.y + pz * r.z;
        float d = (-2.0f * dot + n1) + r.w;
        if (d < d2) {
            if (d < d1) {
                d2 = d1; i2 = i1;
                if (d < d0) { d1 = d0; i1 = i0; d0 = d; i0 = s; }
                else        { d1 = d;  i1 = s; }
            } else { d2 = d; i2 = s; }
        }
    }

    float r0 = 1.0f / (d0 + 1e-8f);
    float r1 = 1.0f / (d1 + 1e-8f);
    float r2 = 1.0f / (d2 + 1e-8f);
    float rs = r0 + r1 + r2;
    float w0 = r0 / rs, w1 = r1 / rs, w2 = r2 / rs;

    const float4* p0 = (const float4*)&g_p2t[((size_t)b * SP + i0) * CIN];
    const float4* p1 = (const float4*)&g_p2t[((size_t)b * SP + i1) * CIN];
    const float4* p2 = (const float4*)&g_p2t[((size_t)b * SP + i2) * CIN];
    size_t mof = ((size_t)b * NP + n) * C0 + CSK;
#pragma unroll 4
    for (int c = 0; c < CIN / 4; c++) {
        float4 a = p0[c], bq = p1[c], cq = p2[c];
        float4 o;
        o.x = a.x * w0 + bq.x * w1 + cq.x * w2;
        o.y = a.y * w0 + bq.y * w1 + cq.y * w2;
        o.z = a.z * w0 + bq.z * w1 + cq.z * w2;
        o.w = a.w * w0 + bq.w * w1 + cq.w * w2;
        __nv_bfloat16 h[4], l[4];
        split2(o.x, h[0], l[0]); split2(o.y, h[1], l[1]);
        split2(o.z, h[2], l[2]); split2(o.w, h[3], l[3]);
        *(uint2*)(g_A0h + mof + c * 4) = *(uint2*)h;
        *(uint2*)(g_A0l + mof + c * 4) = *(uint2*)l;
    }
}

// ---------------------------------------------------------------------------
// Tensor-core GEMM on pre-split bf16 hi/lo planes (3 products).
//   C[m,o] = sum_k A[m,k]*W[o,k] + bias[o]
// BM=BN=128, BK=32, 256 threads (8 warps: 2m x 4n, 64x32 warp tile).
// Hot loop: LDG(bf16) -> STS -> ldmatrix -> 3x HMMA. No conversion math.
// ---------------------------------------------------------------------------
constexpr int ASTR = 40;  // smem row stride (bf16)

template <int K, int ON, int STAGE>
__global__ __launch_bounds__(256) void gemm_mma(const float* __restrict__ bias) {
    constexpr int NB = K / 32;

    __shared__ __nv_bfloat16 sAhi[128][ASTR], sAlo[128][ASTR];
    __shared__ __nv_bfloat16 sWhi[128][ASTR], sWlo[128][ASTR];

    const __nv_bfloat16* Ah = (STAGE == 0) ? g_A0h : (STAGE == 1 ? g_X1h : g_X2h);
    const __nv_bfloat16* Al = (STAGE == 0) ? g_A0l : (STAGE == 1 ? g_X1l : g_X2l);
    const __nv_bfloat16* Wh = (STAGE == 0) ? g_W0h : (STAGE == 1 ? g_W1h : g_W2h);
    const __nv_bfloat16* Wl = (STAGE == 0) ? g_W0l : (STAGE == 1 ? g_W1l : g_W2l);
    float*               Co = (STAGE == 0) ? g_y1  : (STAGE == 1 ? g_h1  : g_h2);

    const int tid  = threadIdx.x;
    const int m0   = blockIdx.x * 128;
    const int n0   = blockIdx.y * 128;
    const int b    = m0 >> 13;  // NP = 8192
    const int lane = tid & 31;
    const int warp = tid >> 5;
    const int wm   = (warp & 1) * 64;   // warp m-offset
    const int wn   = (warp >> 1) * 32;  // warp n-offset

    // global->reg staging: idx = q*256+tid -> row = idx>>2, col8 = (idx&3)*8
    uint4 rAh[2], rAl[2], rWh[2], rWl[2];
    auto load_regs = [&](int kb) {
        int k0 = kb * 32;
#pragma unroll
        for (int q = 0; q < 2; q++) {
            int idx = q * 256 + tid;
            int row = idx >> 2, c8 = (idx & 3) * 8;
            size_t ao = (size_t)(m0 + row) * K + k0 + c8;
            size_t wo = (size_t)(n0 + row) * K + k0 + c8;
            rAh[q] = *(const uint4*)(Ah + ao);
            rAl[q] = *(const uint4*)(Al + ao);
            rWh[q] = *(const uint4*)(Wh + wo);
            rWl[q] = *(const uint4*)(Wl + wo);
        }
    };
    auto store_smem = [&]() {
#pragma unroll
        for (int q = 0; q < 2; q++) {
            int idx = q * 256 + tid;
            int row = idx >> 2, c8 = (idx & 3) * 8;
            *(uint4*)&sAhi[row][c8] = rAh[q];
            *(uint4*)&sAlo[row][c8] = rAl[q];
            *(uint4*)&sWhi[row][c8] = rWh[q];
            *(uint4*)&sWlo[row][c8] = rWl[q];
        }
    };

    float c[4][4][4];
#pragma unroll
    for (int i = 0; i < 4; i++)
#pragma unroll
        for (int j = 0; j < 4; j++)
#pragma unroll
            for (int r = 0; r < 4; r++) c[i][j][r] = 0.0f;

    const int lr15 = lane & 15;
    const int lk8  = (lane >> 4) << 3;
    const uint32_t aHiB = sptr(sAhi), aLoB = sptr(sAlo);
    const uint32_t wHiB = sptr(sWhi), wLoB = sptr(sWlo);

    load_regs(0);
    store_smem();
    __syncthreads();

    for (int kb = 0; kb < NB; kb++) {
        if (kb + 1 < NB) load_regs(kb + 1);

#pragma unroll
        for (int ks = 0; ks < 32; ks += 16) {
            uint32_t ah[4][4], al[4][4], wh[4][2], wl[4][2];
#pragma unroll
            for (int i = 0; i < 4; i++) {
                uint32_t off = (uint32_t)((wm + i * 16 + lr15) * ASTR + ks + lk8) * 2;
                ldmx4(ah[i], aHiB + off);
                ldmx4(al[i], aLoB + off);
            }
#pragma unroll
            for (int p = 0; p < 2; p++) {
                uint32_t off = (uint32_t)((wn + p * 16 + lr15) * ASTR + ks + lk8) * 2;
                uint32_t r[4];
                ldmx4(r, wHiB + off);
                wh[2 * p][0] = r[0]; wh[2 * p][1] = r[2];
                wh[2 * p + 1][0] = r[1]; wh[2 * p + 1][1] = r[3];
                ldmx4(r, wLoB + off);
                wl[2 * p][0] = r[0]; wl[2 * p][1] = r[2];
                wl[2 * p + 1][0] = r[1]; wl[2 * p + 1][1] = r[3];
            }
#pragma unroll
            for (int i = 0; i < 4; i++)
#pragma unroll
                for (int j = 0; j < 4; j++) {
                    mma16816(c[i][j], ah[i], wh[j]);
                    mma16816(c[i][j], ah[i], wl[j]);
                    mma16816(c[i][j], al[i], wh[j]);
                }
        }
        __syncthreads();
        if (kb + 1 < NB) {
            store_smem();
            __syncthreads();
        }
    }

    // Epilogue: +bias, store fp32, accumulate GN stats (whole warp -> one group)
    float s = 0.0f, s2 = 0.0f;
#pragma unroll
    for (int i = 0; i < 4; i++) {
#pragma unroll
        for (int j = 0; j < 4; j++) {
            int row = m0 + wm + i * 16 + (lane >> 2);
            int col = n0 + wn + j * 8 + (lane & 3) * 2;
            float b0 = __ldg(bias + col), b1 = __ldg(bias + col + 1);
            float v0 = c[i][j][0] + b0, v1 = c[i][j][1] + b1;
            float v2 = c[i][j][2] + b0, v3 = c[i][j][3] + b1;
            *(float2*)&Co[(size_t)row * ON + col]       = make_float2(v0, v1);
            *(float2*)&Co[(size_t)(row + 8) * ON + col] = make_float2(v2, v3);
            s  += v0 + v1 + v2 + v3;
            s2 += v0 * v0 + v1 * v1 + v2 * v2 + v3 * v3;
        }
    }
#pragma unroll
    for (int off = 16; off >= 1; off >>= 1) {
        s  += __shfl_xor_sync(0xffffffffu, s,  off);
        s2 += __shfl_xor_sync(0xffffffffu, s2, off);
    }
    if (lane == 0) {
        int g = (n0 + wn) / (ON / 8);
        atomicAdd(&g_sum[STAGE * 64 + b * 8 + g], s);
        atomicAdd(&g_sqs[STAGE * 64 + b * 8 + g], s2);
    }
}

// ---------------------------------------------------------------------------
// Finalize GN stats -> per-(b,c) affine coefs: x*a + bb == gn(x)*gw+gb
// ---------------------------------------------------------------------------
template <int STAGE, int CCH>
__global__ void finalize_k(const float* __restrict__ gw, const float* __restrict__ gb) {
    int b = blockIdx.x, c = threadIdx.x;
    int g = c / (CCH / 8);
    float cnt  = (float)(CCH / 8) * (float)NP;
    float mean = g_sum[STAGE * 64 + b * 8 + g] / cnt;
    float var  = g_sqs[STAGE * 64 + b * 8 + g] / cnt - mean * mean;
    float rstd = rsqrtf(var + 1e-5f);
    float a  = rstd * gw[c];
    float bb = gb[c] - mean * a;
    if      (STAGE == 0) { g_cA0[b * CCH + c] = a; g_cB0[b * CCH + c] = bb; }
    else if (STAGE == 1) { g_cA1[b * CCH + c] = a; g_cB1[b * CCH + c] = bb; }
    else                 { g_cA2[b * CCH + c] = a; g_cB2[b * CCH + c] = bb; }
}

// ---------------------------------------------------------------------------
// Final: out[b,c,n] = gn2(h2)*(1+scale)+shift + silu(gn0(y1))  (with transpose)
// ---------------------------------------------------------------------------
__global__ void final_k(float* __restrict__ out) {
    __shared__ float t[32][33];
    int b  = blockIdx.z;
    int n0 = blockIdx.x * 32;
    int c0 = blockIdx.y * 32;
    int tx = threadIdx.x, ty = threadIdx.y;
#pragma unroll
    for (int i = 0; i < 4; i++) {
        int nl = ty + i * 8;
        size_t m = (size_t)b * NP + n0 + nl;
        int c = c0 + tx;
        float h2 = g_h2[m * C1 + c];
        float hn = h2 * g_cA2[b * C1 + c] + g_cB2[b * C1 + c];
        float y1 = g_y1[m * C1 + c];
        float idn = silu_f(y1 * g_cA0[b * C1 + c] + g_cB0[b * C1 + c]);
        float v = hn * (1.0f + g_scale[b * C1 + c]) + g_shift[b * C1 + c] + idn;
        t[nl][tx] = v;
    }
    __syncthreads();
#pragma unroll
    for (int i = 0; i < 4; i++) {
        int cl = ty + i * 8;
        out[((size_t)b * C1 + c0 + cl) * NP + n0 + tx] = t[tx][cl];
    }
}

// ---------------------------------------------------------------------------
// Launch
// ---------------------------------------------------------------------------
extern "C" void kernel_launch(void* const* d_in, const int* in_sizes, int n_in,
                              void* d_out, int out_size) {
    (void)in_sizes; (void)n_in; (void)out_size;
    const float* xyz1    = (const float*)d_in[0];
    const float* points1 = (const float*)d_in[1];
    const float* xyz2    = (const float*)d_in[2];
    const float* points2 = (const float*)d_in[3];
    const float* t_emb   = (const float*)d_in[4];
    const float* c_emb   = (const float*)d_in[5];
    const float* mlp_w   = (const float*)d_in[6];
    const float* mlp_b   = (const float*)d_in[7];
    const float* mlp_gw  = (const float*)d_in[8];
    const float* mlp_gb  = (const float*)d_in[9];
    const float* c1w     = (const float*)d_in[10];
    const float* c1b     = (const float*)d_in[11];
    const float* g1w     = (const float*)d_in[12];
    const float* g1b     = (const float*)d_in[13];
    const float* c2w     = (const float*)d_in[14];
    const float* c2b     = (const float*)d_in[15];
    const float* g2w     = (const float*)d_in[16];
    const float* g2b     = (const float*)d_in[17];
    const float* tw      = (const float*)d_in[18];
    const float* tb      = (const float*)d_in[19];
    const float* cw      = (const float*)d_in[20];
    const float* cb      = (const float*)d_in[21];
    float* out = (float*)d_out;

    zero_k<<<1, 256>>>();
    wsplit_k<0><<<(C1 * C0 / 8 + 255) / 256, 256>>>(mlp_w, C1 * C0 / 8);
    wsplit_k<1><<<(CE * C1 / 8 + 255) / 256, 256>>>(c1w, CE * C1 / 8);
    wsplit_k<2><<<(C1 * CE / 8 + 255) / 256, 256>>>(c2w, C1 * CE / 8);
    tr_p1_k<<<dim3(NP / 32, CSK / 32, BB), dim3(32, 8)>>>(points1);
    tr_p2_k<<<dim3(SP / 32, CIN / 32, BB), dim3(32, 8)>>>(points2);
    emb_k<<<512, 256>>>(t_emb, c_emb, tw, tb, cw, cb);
    knn_k<<<dim3(NP / 128, BB), 128>>>(xyz1, xyz2);

    gemm_mma<C0, C1, 0><<<dim3(MTOT / 128, C1 / 128), 256>>>(mlp_b);
    finalize_k<0, C1><<<BB, C1>>>(mlp_gw, mlp_gb);
    asplit_k<1><<<MTOT * C1 / 8 / 256, 256>>>();

    gemm_mma<C1, CE, 1><<<dim3(MTOT / 128, CE / 128), 256>>>(c1b);
    finalize_k<1, CE><<<BB, CE>>>(g1w, g1b);
    asplit_k<2><<<MTOT * CE / 8 / 256, 256>>>();

    gemm_mma<CE, C1, 2><<<dim3(MTOT / 128, C1 / 128), 256>>>(c2b);
    finalize_k<2, C1><<<BB, C1>>>(g2w, g2b);

    final_k<<<dim3(NP / 32, C1 / 32, BB), dim3(32, 8)>>>(out);
}

// round 11
// speedup vs baseline: 1.6825x; 1.1128x over previous
#include <cuda_runtime.h>
#include <cuda_bf16.h>
#include <cstdint>

// ---------------------------------------------------------------------------
// Problem constants
// ---------------------------------------------------------------------------
constexpr int BB   = 8;
constexpr int NP   = 8192;
constexpr int SP   = 2048;
constexpr int CIN  = 256;
constexpr int CSK  = 128;
constexpr int C0   = 384;     // IN+SKIP
constexpr int C1   = 256;     // OUT
constexpr int CE   = 1024;    // OUT*EXP
constexpr int MTOT = BB * NP; // 65536 rows

// ---------------------------------------------------------------------------
// Scratch (device globals; no dynamic allocation allowed)
// ---------------------------------------------------------------------------
static __device__ __nv_bfloat16 g_A0h[MTOT * C0], g_A0l[MTOT * C0]; // stage0 A planes
static __device__ __nv_bfloat16 g_X1h[MTOT * C1], g_X1l[MTOT * C1]; // stage1 A planes
static __device__ __nv_bfloat16 g_X2h[MTOT * CE], g_X2l[MTOT * CE]; // stage2 A planes
static __device__ __nv_bfloat16 g_W0h[C1 * C0], g_W0l[C1 * C0];
static __device__ __nv_bfloat16 g_W1h[CE * C1], g_W1l[CE * C1];
static __device__ __nv_bfloat16 g_W2h[C1 * CE], g_W2l[C1 * CE];
static __device__ float g_p2t[BB * SP * CIN];  // points2 transposed [b, s, c]
static __device__ float g_y1 [MTOT * C1];      // conv0 out (pre-GN)
static __device__ float g_h1 [MTOT * CE];      // conv1 out (pre-GN)
static __device__ float g_h2 [MTOT * C1];      // conv2 out (pre-GN)
static __device__ float g_sum[3 * 64];
static __device__ float g_sqs[3 * 64];
static __device__ float g_cA0[BB * C1], g_cB0[BB * C1];
static __device__ float g_cA1[BB * CE], g_cB1[BB * CE];
static __device__ float g_cA2[BB * C1], g_cB2[BB * C1];
static __device__ float g_scale[BB * C1], g_shift[BB * C1];

__device__ __forceinline__ float silu_f(float x) {
    return __fdividef(x, 1.0f + __expf(-x));
}
__device__ __forceinline__ void split2(float x, __nv_bfloat16& h, __nv_bfloat16& l) {
    h = __float2bfloat16(x);
    l = __float2bfloat16(x - __bfloat162float(h));
}

// ---------------------------------------------------------------------------
// MMA / cp.async helpers (legacy bf16 tensor-core path; plain sm_100 target)
// ---------------------------------------------------------------------------
__device__ __forceinline__ uint32_t sptr(const void* p) {
    return (uint32_t)__cvta_generic_to_shared(p);
}
__device__ __forceinline__ void ldmx4(uint32_t* r, uint32_t addr) {
    asm volatile("ldmatrix.sync.aligned.m8n8.x4.shared.b16 {%0,%1,%2,%3}, [%4];\n"
                 : "=r"(r[0]), "=r"(r[1]), "=r"(r[2]), "=r"(r[3]) : "r"(addr));
}
__device__ __forceinline__ void mma16816(float* c, const uint32_t* a, const uint32_t* b) {
    asm volatile(
        "mma.sync.aligned.m16n8k16.row.col.f32.bf16.bf16.f32 "
        "{%0,%1,%2,%3}, {%4,%5,%6,%7}, {%8,%9}, {%0,%1,%2,%3};\n"
        : "+f"(c[0]), "+f"(c[1]), "+f"(c[2]), "+f"(c[3])
        : "r"(a[0]), "r"(a[1]), "r"(a[2]), "r"(a[3]), "r"(b[0]), "r"(b[1]));
}
__device__ __forceinline__ void cp16(uint32_t dst, const void* src) {
    asm volatile("cp.async.cg.shared.global [%0], [%1], 16;\n" :: "r"(dst), "l"(src));
}
__device__ __forceinline__ void cp_commit() {
    asm volatile("cp.async.commit_group;\n" ::: "memory");
}
template <int N>
__device__ __forceinline__ void cp_wait() {
    asm volatile("cp.async.wait_group %0;\n" :: "n"(N) : "memory");
}

// ---------------------------------------------------------------------------
// Zero the stats accumulators
// ---------------------------------------------------------------------------
__global__ void zero_k() {
    int i = threadIdx.x;
    if (i < 192) { g_sum[i] = 0.0f; g_sqs[i] = 0.0f; }
}

// ---------------------------------------------------------------------------
// Weight split: fp32 -> bf16 hi/lo planes.
// ---------------------------------------------------------------------------
template <int WS>
__global__ void wsplit_k(const float* __restrict__ w, int n8) {
    int i = blockIdx.x * 256 + threadIdx.x;
    if (i >= n8) return;
    __nv_bfloat16* hi = (WS == 0) ? g_W0h : (WS == 1 ? g_W1h : g_W2h);
    __nv_bfloat16* lo = (WS == 0) ? g_W0l : (WS == 1 ? g_W1l : g_W2l);
    const float4* wp = (const float4*)w + 2 * i;
    float4 a = wp[0], b = wp[1];
    __nv_bfloat16 h[8], l[8];
    split2(a.x, h[0], l[0]); split2(a.y, h[1], l[1]);
    split2(a.z, h[2], l[2]); split2(a.w, h[3], l[3]);
    split2(b.x, h[4], l[4]); split2(b.y, h[5], l[5]);
    split2(b.z, h[6], l[6]); split2(b.w, h[7], l[7]);
    *(uint4*)(hi + (size_t)i * 8) = *(uint4*)h;
    *(uint4*)(lo + (size_t)i * 8) = *(uint4*)l;
}

// ---------------------------------------------------------------------------
// Activation split: x -> silu(x*cA + cB) -> bf16 hi/lo planes (8 elems/thread)
// ---------------------------------------------------------------------------
template <int STAGE>
__global__ void asplit_k() {
    constexpr int C = (STAGE == 1) ? C1 : CE;
    const float* X  = (STAGE == 1) ? g_y1  : g_h1;
    const float* cA = (STAGE == 1) ? g_cA0 : g_cA1;
    const float* cB = (STAGE == 1) ? g_cB0 : g_cB1;
    __nv_bfloat16* oh = (STAGE == 1) ? g_X1h : g_X2h;
    __nv_bfloat16* ol = (STAGE == 1) ? g_X1l : g_X2l;

    size_t i = (size_t)blockIdx.x * 256 + threadIdx.x;   // per 8 elements
    int m  = (int)(i / (C / 8));
    int c0 = (int)(i % (C / 8)) * 8;
    int b  = m >> 13;
    const float4* xp = (const float4*)(X + (size_t)m * C + c0);
    float4 x0 = xp[0], x1 = xp[1];
    const float* a = cA + b * C + c0;
    const float* s = cB + b * C + c0;
    float v[8];
    v[0] = silu_f(x0.x * a[0] + s[0]); v[1] = silu_f(x0.y * a[1] + s[1]);
    v[2] = silu_f(x0.z * a[2] + s[2]); v[3] = silu_f(x0.w * a[3] + s[3]);
    v[4] = silu_f(x1.x * a[4] + s[4]); v[5] = silu_f(x1.y * a[5] + s[5]);
    v[6] = silu_f(x1.z * a[6] + s[6]); v[7] = silu_f(x1.w * a[7] + s[7]);
    __nv_bfloat16 h[8], l[8];
#pragma unroll
    for (int j = 0; j < 8; j++) split2(v[j], h[j], l[j]);
    *(uint4*)(oh + (size_t)m * C + c0) = *(uint4*)h;
    *(uint4*)(ol + (size_t)m * C + c0) = *(uint4*)l;
}

// ---------------------------------------------------------------------------
// Transpose points1 [B,128,N] -> stage0 A planes, columns [0,128)
// ---------------------------------------------------------------------------
__global__ void tr_p1_k(const float* __restrict__ src) {
    __shared__ float t[32][33];
    int b  = blockIdx.z;
    int n0 = blockIdx.x * 32;
    int c0 = blockIdx.y * 32;
    int tx = threadIdx.x, ty = threadIdx.y;
#pragma unroll
    for (int i = 0; i < 4; i++) {
        int cl = ty + i * 8;
        t[cl][tx] = src[((size_t)b * CSK + (c0 + cl)) * NP + n0 + tx];
    }
    __syncthreads();
#pragma unroll
    for (int i = 0; i < 4; i++) {
        int nl = ty + i * 8;
        size_t m = (size_t)b * NP + n0 + nl;
        __nv_bfloat16 h, l;
        split2(t[tx][nl], h, l);
        g_A0h[m * C0 + c0 + tx] = h;
        g_A0l[m * C0 + c0 + tx] = l;
    }
}

// ---------------------------------------------------------------------------
// Transpose points2 [B,256,S] -> g_p2t [b, s, c]
// ---------------------------------------------------------------------------
__global__ void tr_p2_k(const float* __restrict__ src) {
    __shared__ float t[32][33];
    int b  = blockIdx.z;
    int s0 = blockIdx.x * 32;
    int c0 = blockIdx.y * 32;
    int tx = threadIdx.x, ty = threadIdx.y;
#pragma unroll
    for (int i = 0; i < 4; i++) {
        int cl = ty + i * 8;
        t[cl][tx] = src[((size_t)b * CIN + (c0 + cl)) * SP + s0 + tx];
    }
    __syncthreads();
#pragma unroll
    for (int i = 0; i < 4; i++) {
        int sl = ty + i * 8;
        g_p2t[((size_t)b * SP + (s0 + sl)) * CIN + c0 + tx] = t[tx][sl];
    }
}

// ---------------------------------------------------------------------------
// Embedding modulation: one warp per (b, output-row j)
// ---------------------------------------------------------------------------
__global__ void emb_k(const float* __restrict__ t_emb, const float* __restrict__ c_emb,
                      const float* __restrict__ tw, const float* __restrict__ tb,
                      const float* __restrict__ cw, const float* __restrict__ cb) {
    int gw   = (blockIdx.x * blockDim.x + threadIdx.x) >> 5;
    int lane = threadIdx.x & 31;
    int b = gw >> 9;
    int j = gw & 511;
    const float* twr = tw + (size_t)j * C1;
    const float* cwr = cw + (size_t)j * C1;
    const float* te  = t_emb + b * C1;
    const float* ce  = c_emb + b * C1;
    int k0 = lane * 8;
    float4 a0 = *(const float4*)(twr + k0);
    float4 a1 = *(const float4*)(twr + k0 + 4);
    float4 b0 = *(const float4*)(cwr + k0);
    float4 b1 = *(const float4*)(cwr + k0 + 4);
    float4 t0 = *(const float4*)(te + k0);
    float4 t1 = *(const float4*)(te + k0 + 4);
    float4 c0 = *(const float4*)(ce + k0);
    float4 c1 = *(const float4*)(ce + k0 + 4);
    float s = a0.x * t0.x + a0.y * t0.y + a0.z * t0.z + a0.w * t0.w
            + a1.x * t1.x + a1.y * t1.y + a1.z * t1.z + a1.w * t1.w
            + b0.x * c0.x + b0.y * c0.y + b0.z * c0.z + b0.w * c0.w
            + b1.x * c1.x + b1.y * c1.y + b1.z * c1.z + b1.w * c1.w;
#pragma unroll
    for (int off = 16; off >= 1; off >>= 1) s += __shfl_xor_sync(0xffffffffu, s, off);
    if (lane == 0) {
        s += tb[j] + cb[j];
        if (j < C1) g_scale[b * C1 + j] = s;
        else        g_shift[b * C1 + (j - C1)] = s;
    }
}

// ---------------------------------------------------------------------------
// 3-NN + inverse-distance interpolation -> stage0 A planes cols [128,384)
// ---------------------------------------------------------------------------
__global__ void knn_k(const float* __restrict__ xyz1, const float* __restrict__ xyz2) {
    __shared__ float4 ref[SP];
    int b = blockIdx.y;
    int n = blockIdx.x * 128 + threadIdx.x;
    for (int s = threadIdx.x; s < SP; s += 128) {
        float x = xyz2[((size_t)b * 3 + 0) * SP + s];
        float y = xyz2[((size_t)b * 3 + 1) * SP + s];
        float z = xyz2[((size_t)b * 3 + 2) * SP + s];
        ref[s] = make_float4(x, y, z, x * x + y * y + z * z);
    }
    __syncthreads();

    float px = xyz1[((size_t)b * 3 + 0) * NP + n];
    float py = xyz1[((size_t)b * 3 + 1) * NP + n];
    float pz = xyz1[((size_t)b * 3 + 2) * NP + n];
    float n1 = px * px + py * py + pz * pz;

    float d0 = 3.4e38f, d1 = 3.4e38f, d2 = 3.4e38f;
    int   i0 = 0, i1 = 0, i2 = 0;
    for (int s = 0; s < SP; s++) {
        float4 r = ref[s];
        float dot = px * r.x + py * r.y + pz * r.z;
        float d = (-2.0f * dot + n1) + r.w;
        if (d < d2) {
            if (d < d1) {
                d2 = d1; i2 = i1;
                if (d < d0) { d1 = d0; i1 = i0; d0 = d; i0 = s; }
                else        { d1 = d;  i1 = s; }
            } else { d2 = d; i2 = s; }
        }
    }

    float r0 = 1.0f / (d0 + 1e-8f);
    float r1 = 1.0f / (d1 + 1e-8f);
    float r2 = 1.0f / (d2 + 1e-8f);
    float rs = r0 + r1 + r2;
    float w0 = r0 / rs, w1 = r1 / rs, w2 = r2 / rs;

    const float4* p0 = (const float4*)&g_p2t[((size_t)b * SP + i0) * CIN];
    const float4* p1 = (const float4*)&g_p2t[((size_t)b * SP + i1) * CIN];
    const float4* p2 = (const float4*)&g_p2t[((size_t)b * SP + i2) * CIN];
    size_t mof = ((size_t)b * NP + n) * C0 + CSK;
#pragma unroll 4
    for (int c = 0; c < CIN / 4; c++) {
        float4 a = p0[c], bq = p1[c], cq = p2[c];
        float4 o;
        o.x = a.x * w0 + bq.x * w1 + cq.x * w2;
        o.y = a.y * w0 + bq.y * w1 + cq.y * w2;
        o.z = a.z * w0 + bq.z * w1 + cq.z * w2;
        o.w = a.w * w0 + bq.w * w1 + cq.w * w2;
        __nv_bfloat16 h[4], l[4];
        split2(o.x, h[0], l[0]); split2(o.y, h[1], l[1]);
        split2(o.z, h[2], l[2]); split2(o.w, h[3], l[3]);
        *(uint2*)(g_A0h + mof + c * 4) = *(uint2*)h;
        *(uint2*)(g_A0l + mof + c * 4) = *(uint2*)l;
    }
}

// ---------------------------------------------------------------------------
// Tensor-core GEMM on pre-split bf16 hi/lo planes (3 products),
// 2-stage cp.async pipeline: MMA on buffer b overlaps fill of buffer b^1.
//   C[m,o] = sum_k A[m,k]*W[o,k] + bias[o]
// BM=BN=128, BK=32, 256 threads (8 warps: 2m x 4n, 64x32 warp tile).
// ---------------------------------------------------------------------------
constexpr int ASTR = 40;                 // smem row stride (bf16)
constexpr int PL   = 128 * ASTR * 2;     // one plane: 10240 B
constexpr int BUFB = 4 * PL;             // Ahi,Alo,Whi,Wlo: 40960 B
constexpr int GSM  = 2 * BUFB;           // 81920 B dynamic smem

template <int K, int ON, int STAGE>
__global__ __launch_bounds__(256) void gemm_mma(const float* __restrict__ bias) {
    constexpr int NB = K / 32;
    extern __shared__ char smdyn[];

    const __nv_bfloat16* Ah = (STAGE == 0) ? g_A0h : (STAGE == 1 ? g_X1h : g_X2h);
    const __nv_bfloat16* Al = (STAGE == 0) ? g_A0l : (STAGE == 1 ? g_X1l : g_X2l);
    const __nv_bfloat16* Wh = (STAGE == 0) ? g_W0h : (STAGE == 1 ? g_W1h : g_W2h);
    const __nv_bfloat16* Wl = (STAGE == 0) ? g_W0l : (STAGE == 1 ? g_W1l : g_W2l);
    float*               Co = (STAGE == 0) ? g_y1  : (STAGE == 1 ? g_h1  : g_h2);

    const int tid  = threadIdx.x;
    const int m0   = blockIdx.x * 128;
    const int n0   = blockIdx.y * 128;
    const int b    = m0 >> 13;  // NP = 8192
    const int lane = tid & 31;
    const int warp = tid >> 5;
    const int wm   = (warp & 1) * 64;   // warp m-offset
    const int wn   = (warp >> 1) * 32;  // warp n-offset

    const uint32_t sb = sptr(smdyn);

    // cp.async staging: idx = q*256+tid -> row = idx>>2, col8 = (idx&3)*8
    uint32_t soff[2];
    const __nv_bfloat16 *pAh[2], *pAl[2], *pWh[2], *pWl[2];
#pragma unroll
    for (int q = 0; q < 2; q++) {
        int idx = q * 256 + tid;
        int row = idx >> 2, c8 = (idx & 3) * 8;
        soff[q] = (uint32_t)(row * ASTR + c8) * 2;
        size_t ao = (size_t)(m0 + row) * K + c8;
        size_t wo = (size_t)(n0 + row) * K + c8;
        pAh[q] = Ah + ao; pAl[q] = Al + ao;
        pWh[q] = Wh + wo; pWl[q] = Wl + wo;
    }
    auto issue_tile = [&](int kb, int bs) {
        int k0 = kb * 32;
        uint32_t base = sb + bs * BUFB;
#pragma unroll
        for (int q = 0; q < 2; q++) {
            uint32_t d = base + soff[q];
            cp16(d + 0 * PL, pAh[q] + k0);
            cp16(d + 1 * PL, pAl[q] + k0);
            cp16(d + 2 * PL, pWh[q] + k0);
            cp16(d + 3 * PL, pWl[q] + k0);
        }
    };

    float c[4][4][4];
#pragma unroll
    for (int i = 0; i < 4; i++)
#pragma unroll
        for (int j = 0; j < 4; j++)
#pragma unroll
            for (int r = 0; r < 4; r++) c[i][j][r] = 0.0f;

    const int lr15 = lane & 15;
    const int lk8  = (lane >> 4) << 3;

    issue_tile(0, 0);
    cp_commit();

    for (int kb = 0; kb < NB; kb++) {
        int bs = kb & 1;
        if (kb + 1 < NB) {
            issue_tile(kb + 1, bs ^ 1);
            cp_commit();
            cp_wait<1>();
        } else {
            cp_wait<0>();
        }
        __syncthreads();

        uint32_t bufbase = sb + bs * BUFB;
        uint32_t aHiB = bufbase + 0 * PL, aLoB = bufbase + 1 * PL;
        uint32_t wHiB = bufbase + 2 * PL, wLoB = bufbase + 3 * PL;

#pragma unroll
        for (int ks = 0; ks < 32; ks += 16) {
            uint32_t ah[4][4], al[4][4], wh[4][2], wl[4][2];
#pragma unroll
            for (int i = 0; i < 4; i++) {
                uint32_t off = (uint32_t)((wm + i * 16 + lr15) * ASTR + ks + lk8) * 2;
                ldmx4(ah[i], aHiB + off);
                ldmx4(al[i], aLoB + off);
            }
#pragma unroll
            for (int p = 0; p < 2; p++) {
                uint32_t off = (uint32_t)((wn + p * 16 + lr15) * ASTR + ks + lk8) * 2;
                uint32_t r[4];
                ldmx4(r, wHiB + off);
                wh[2 * p][0] = r[0]; wh[2 * p][1] = r[2];
                wh[2 * p + 1][0] = r[1]; wh[2 * p + 1][1] = r[3];
                ldmx4(r, wLoB + off);
                wl[2 * p][0] = r[0]; wl[2 * p][1] = r[2];
                wl[2 * p + 1][0] = r[1]; wl[2 * p + 1][1] = r[3];
            }
#pragma unroll
            for (int i = 0; i < 4; i++)
#pragma unroll
                for (int j = 0; j < 4; j++) {
                    mma16816(c[i][j], ah[i], wh[j]);
                    mma16816(c[i][j], ah[i], wl[j]);
                    mma16816(c[i][j], al[i], wh[j]);
                }
        }
        __syncthreads();   // all warps done reading buf bs before it is refilled
    }

    // Epilogue: +bias, store fp32, accumulate GN stats (whole warp -> one group)
    float s = 0.0f, s2 = 0.0f;
#pragma unroll
    for (int i = 0; i < 4; i++) {
#pragma unroll
        for (int j = 0; j < 4; j++) {
            int row = m0 + wm + i * 16 + (lane >> 2);
            int col = n0 + wn + j * 8 + (lane & 3) * 2;
            float b0 = __ldg(bias + col), b1 = __ldg(bias + col + 1);
            float v0 = c[i][j][0] + b0, v1 = c[i][j][1] + b1;
            float v2 = c[i][j][2] + b0, v3 = c[i][j][3] + b1;
            *(float2*)&Co[(size_t)row * ON + col]       = make_float2(v0, v1);
            *(float2*)&Co[(size_t)(row + 8) * ON + col] = make_float2(v2, v3);
            s  += v0 + v1 + v2 + v3;
            s2 += v0 * v0 + v1 * v1 + v2 * v2 + v3 * v3;
        }
    }
#pragma unroll
    for (int off = 16; off >= 1; off >>= 1) {
        s  += __shfl_xor_sync(0xffffffffu, s,  off);
        s2 += __shfl_xor_sync(0xffffffffu, s2, off);
    }
    if (lane == 0) {
        int g = (n0 + wn) / (ON / 8);
        atomicAdd(&g_sum[STAGE * 64 + b * 8 + g], s);
        atomicAdd(&g_sqs[STAGE * 64 + b * 8 + g], s2);
    }
}

// ---------------------------------------------------------------------------
// Finalize GN stats -> per-(b,c) affine coefs: x*a + bb == gn(x)*gw+gb
// ---------------------------------------------------------------------------
template <int STAGE, int CCH>
__global__ void finalize_k(const float* __restrict__ gw, const float* __restrict__ gb) {
    int b = blockIdx.x, c = threadIdx.x;
    int g = c / (CCH / 8);
    float cnt  = (float)(CCH / 8) * (float)NP;
    float mean = g_sum[STAGE * 64 + b * 8 + g] / cnt;
    float var  = g_sqs[STAGE * 64 + b * 8 + g] / cnt - mean * mean;
    float rstd = rsqrtf(var + 1e-5f);
    float a  = rstd * gw[c];
    float bb = gb[c] - mean * a;
    if      (STAGE == 0) { g_cA0[b * CCH + c] = a; g_cB0[b * CCH + c] = bb; }
    else if (STAGE == 1) { g_cA1[b * CCH + c] = a; g_cB1[b * CCH + c] = bb; }
    else                 { g_cA2[b * CCH + c] = a; g_cB2[b * CCH + c] = bb; }
}

// ---------------------------------------------------------------------------
// Final: out[b,c,n] = gn2(h2)*(1+scale)+shift + silu(gn0(y1))  (with transpose)
// ---------------------------------------------------------------------------
__global__ void final_k(float* __restrict__ out) {
    __shared__ float t[32][33];
    int b  = blockIdx.z;
    int n0 = blockIdx.x * 32;
    int c0 = blockIdx.y * 32;
    int tx = threadIdx.x, ty = threadIdx.y;
#pragma unroll
    for (int i = 0; i < 4; i++) {
        int nl = ty + i * 8;
        size_t m = (size_t)b * NP + n0 + nl;
        int c = c0 + tx;
        float h2 = g_h2[m * C1 + c];
        float hn = h2 * g_cA2[b * C1 + c] + g_cB2[b * C1 + c];
        float y1 = g_y1[m * C1 + c];
        float idn = silu_f(y1 * g_cA0[b * C1 + c] + g_cB0[b * C1 + c]);
        float v = hn * (1.0f + g_scale[b * C1 + c]) + g_shift[b * C1 + c] + idn;
        t[nl][tx] = v;
    }
    __syncthreads();
#pragma unroll
    for (int i = 0; i < 4; i++) {
        int cl = ty + i * 8;
        out[((size_t)b * C1 + c0 + cl) * NP + n0 + tx] = t[tx][cl];
    }
}

// ---------------------------------------------------------------------------
// Launch
// ---------------------------------------------------------------------------
extern "C" void kernel_launch(void* const* d_in, const int* in_sizes, int n_in,
                              void* d_out, int out_size) {
    (void)in_sizes; (void)n_in; (void)out_size;
    const float* xyz1    = (const float*)d_in[0];
    const float* points1 = (const float*)d_in[1];
    const float* xyz2    = (const float*)d_in[2];
    const float* points2 = (const float*)d_in[3];
    const float* t_emb   = (const float*)d_in[4];
    const float* c_emb   = (const float*)d_in[5];
    const float* mlp_w   = (const float*)d_in[6];
    const float* mlp_b   = (const float*)d_in[7];
    const float* mlp_gw  = (const float*)d_in[8];
    const float* mlp_gb  = (const float*)d_in[9];
    const float* c1w     = (const float*)d_in[10];
    const float* c1b     = (const float*)d_in[11];
    const float* g1w     = (const float*)d_in[12];
    const float* g1b     = (const float*)d_in[13];
    const float* c2w     = (const float*)d_in[14];
    const float* c2b     = (const float*)d_in[15];
    const float* g2w     = (const float*)d_in[16];
    const float* g2b     = (const float*)d_in[17];
    const float* tw      = (const float*)d_in[18];
    const float* tb      = (const float*)d_in[19];
    const float* cw      = (const float*)d_in[20];
    const float* cb      = (const float*)d_in[21];
    float* out = (float*)d_out;

    cudaFuncSetAttribute((const void*)gemm_mma<C0, C1, 0>,
                         cudaFuncAttributeMaxDynamicSharedMemorySize, GSM);
    cudaFuncSetAttribute((const void*)gemm_mma<C1, CE, 1>,
                         cudaFuncAttributeMaxDynamicSharedMemorySize, GSM);
    cudaFuncSetAttribute((const void*)gemm_mma<CE, C1, 2>,
                         cudaFuncAttributeMaxDynamicSharedMemorySize, GSM);

    zero_k<<<1, 256>>>();
    wsplit_k<0><<<(C1 * C0 / 8 + 255) / 256, 256>>>(mlp_w, C1 * C0 / 8);
    wsplit_k<1><<<(CE * C1 / 8 + 255) / 256, 256>>>(c1w, CE * C1 / 8);
    wsplit_k<2><<<(C1 * CE / 8 + 255) / 256, 256>>>(c2w, C1 * CE / 8);
    tr_p1_k<<<dim3(NP / 32, CSK / 32, BB), dim3(32, 8)>>>(points1);
    tr_p2_k<<<dim3(SP / 32, CIN / 32, BB), dim3(32, 8)>>>(points2);
    emb_k<<<512, 256>>>(t_emb, c_emb, tw, tb, cw, cb);
    knn_k<<<dim3(NP / 128, BB), 128>>>(xyz1, xyz2);

    gemm_mma<C0, C1, 0><<<dim3(MTOT / 128, C1 / 128), 256, GSM>>>(mlp_b);
    finalize_k<0, C1><<<BB, C1>>>(mlp_gw, mlp_gb);
    asplit_k<1><<<MTOT * C1 / 8 / 256, 256>>>();

    gemm_mma<C1, CE, 1><<<dim3(MTOT / 128, CE / 128), 256, GSM>>>(c1b);
    finalize_k<1, CE><<<BB, CE>>>(g1w, g1b);
    asplit_k<2><<<MTOT * CE / 8 / 256, 256>>>();

    gemm_mma<CE, C1, 2><<<dim3(MTOT / 128, C1 / 128), 256, GSM>>>(c2b);
    finalize_k<2, C1><<<BB, C1>>>(g2w, g2b);

    final_k<<<dim3(NP / 32, C1 / 32, BB), dim3(32, 8)>>>(out);
}

// round 12
// speedup vs baseline: 2.7194x; 1.6163x over previous
#include <cuda_runtime.h>
#include <cuda_fp16.h>
#include <cstdint>

// ---------------------------------------------------------------------------
// Problem constants
// ---------------------------------------------------------------------------
constexpr int BB   = 8;
constexpr int NP   = 8192;
constexpr int SP   = 2048;
constexpr int CIN  = 256;
constexpr int CSK  = 128;
constexpr int C0   = 384;     // IN+SKIP
constexpr int C1   = 256;     // OUT
constexpr int CE   = 1024;    // OUT*EXP
constexpr int MTOT = BB * NP; // 65536 rows

// ---------------------------------------------------------------------------
// Scratch (device globals; no dynamic allocation allowed)
// ---------------------------------------------------------------------------
static __device__ __half g_A0[MTOT * C0];   // stage0 A plane (fp16)
static __device__ __half g_X1[MTOT * C1];   // stage1 A plane
static __device__ __half g_X2[MTOT * CE];   // stage2 A plane
static __device__ __half g_W0[C1 * C0];
static __device__ __half g_W1[CE * C1];
static __device__ __half g_W2[C1 * CE];
static __device__ float g_p2t[BB * SP * CIN];  // points2 transposed [b, s, c]
static __device__ float g_y1 [MTOT * C1];      // conv0 out (pre-GN)
static __device__ float g_h1 [MTOT * CE];      // conv1 out (pre-GN)
static __device__ float g_h2 [MTOT * C1];      // conv2 out (pre-GN)
static __device__ float g_sum[3 * 64];
static __device__ float g_sqs[3 * 64];
static __device__ float g_cA0[BB * C1], g_cB0[BB * C1];
static __device__ float g_cA1[BB * CE], g_cB1[BB * CE];
static __device__ float g_cA2[BB * C1], g_cB2[BB * C1];
static __device__ float g_scale[BB * C1], g_shift[BB * C1];

__device__ __forceinline__ float silu_f(float x) {
    return __fdividef(x, 1.0f + __expf(-x));
}

// ---------------------------------------------------------------------------
// MMA / cp.async helpers (legacy fp16 tensor-core path; plain sm_100 target)
// ---------------------------------------------------------------------------
__device__ __forceinline__ uint32_t sptr(const void* p) {
    return (uint32_t)__cvta_generic_to_shared(p);
}
__device__ __forceinline__ void ldmx4(uint32_t* r, uint32_t addr) {
    asm volatile("ldmatrix.sync.aligned.m8n8.x4.shared.b16 {%0,%1,%2,%3}, [%4];\n"
                 : "=r"(r[0]), "=r"(r[1]), "=r"(r[2]), "=r"(r[3]) : "r"(addr));
}
__device__ __forceinline__ void mma16816(float* c, const uint32_t* a, const uint32_t* b) {
    asm volatile(
        "mma.sync.aligned.m16n8k16.row.col.f32.f16.f16.f32 "
        "{%0,%1,%2,%3}, {%4,%5,%6,%7}, {%8,%9}, {%0,%1,%2,%3};\n"
        : "+f"(c[0]), "+f"(c[1]), "+f"(c[2]), "+f"(c[3])
        : "r"(a[0]), "r"(a[1]), "r"(a[2]), "r"(a[3]), "r"(b[0]), "r"(b[1]));
}
__device__ __forceinline__ void cp16(uint32_t dst, const void* src) {
    asm volatile("cp.async.cg.shared.global [%0], [%1], 16;\n" :: "r"(dst), "l"(src));
}
__device__ __forceinline__ void cp_commit() {
    asm volatile("cp.async.commit_group;\n" ::: "memory");
}
template <int N>
__device__ __forceinline__ void cp_wait() {
    asm volatile("cp.async.wait_group %0;\n" :: "n"(N) : "memory");
}

// ---------------------------------------------------------------------------
// Zero the stats accumulators
// ---------------------------------------------------------------------------
__global__ void zero_k() {
    int i = threadIdx.x;
    if (i < 192) { g_sum[i] = 0.0f; g_sqs[i] = 0.0f; }
}

// ---------------------------------------------------------------------------
// Weight convert: fp32 -> fp16 plane (8 elems/thread)
// ---------------------------------------------------------------------------
template <int WS>
__global__ void wsplit_k(const float* __restrict__ w, int n8) {
    int i = blockIdx.x * 256 + threadIdx.x;
    if (i >= n8) return;
    __half* hi = (WS == 0) ? g_W0 : (WS == 1 ? g_W1 : g_W2);
    const float4* wp = (const float4*)w + 2 * i;
    float4 a = wp[0], b = wp[1];
    __half h[8];
    h[0] = __float2half(a.x); h[1] = __float2half(a.y);
    h[2] = __float2half(a.z); h[3] = __float2half(a.w);
    h[4] = __float2half(b.x); h[5] = __float2half(b.y);
    h[6] = __float2half(b.z); h[7] = __float2half(b.w);
    *(uint4*)(hi + (size_t)i * 8) = *(uint4*)h;
}

// ---------------------------------------------------------------------------
// Activation convert: x -> silu(x*cA + cB) -> fp16 plane (8 elems/thread)
// ---------------------------------------------------------------------------
template <int STAGE>
__global__ void asplit_k() {
    constexpr int C = (STAGE == 1) ? C1 : CE;
    const float* X  = (STAGE == 1) ? g_y1  : g_h1;
    const float* cA = (STAGE == 1) ? g_cA0 : g_cA1;
    const float* cB = (STAGE == 1) ? g_cB0 : g_cB1;
    __half* oh = (STAGE == 1) ? g_X1 : g_X2;

    size_t i = (size_t)blockIdx.x * 256 + threadIdx.x;   // per 8 elements
    int m  = (int)(i / (C / 8));
    int c0 = (int)(i % (C / 8)) * 8;
    int b  = m >> 13;
    const float4* xp = (const float4*)(X + (size_t)m * C + c0);
    float4 x0 = xp[0], x1 = xp[1];
    const float* a = cA + b * C + c0;
    const float* s = cB + b * C + c0;
    __half h[8];
    h[0] = __float2half(silu_f(x0.x * a[0] + s[0]));
    h[1] = __float2half(silu_f(x0.y * a[1] + s[1]));
    h[2] = __float2half(silu_f(x0.z * a[2] + s[2]));
    h[3] = __float2half(silu_f(x0.w * a[3] + s[3]));
    h[4] = __float2half(silu_f(x1.x * a[4] + s[4]));
    h[5] = __float2half(silu_f(x1.y * a[5] + s[5]));
    h[6] = __float2half(silu_f(x1.z * a[6] + s[6]));
    h[7] = __float2half(silu_f(x1.w * a[7] + s[7]));
    *(uint4*)(oh + (size_t)m * C + c0) = *(uint4*)h;
}

// ---------------------------------------------------------------------------
// Transpose points1 [B,128,N] -> stage0 A plane, columns [0,128)
// ---------------------------------------------------------------------------
__global__ void tr_p1_k(const float* __restrict__ src) {
    __shared__ float t[32][33];
    int b  = blockIdx.z;
    int n0 = blockIdx.x * 32;
    int c0 = blockIdx.y * 32;
    int tx = threadIdx.x, ty = threadIdx.y;
#pragma unroll
    for (int i = 0; i < 4; i++) {
        int cl = ty + i * 8;
        t[cl][tx] = src[((size_t)b * CSK + (c0 + cl)) * NP + n0 + tx];
    }
    __syncthreads();
#pragma unroll
    for (int i = 0; i < 4; i++) {
        int nl = ty + i * 8;
        size_t m = (size_t)b * NP + n0 + nl;
        g_A0[m * C0 + c0 + tx] = __float2half(t[tx][nl]);
    }
}

// ---------------------------------------------------------------------------
// Transpose points2 [B,256,S] -> g_p2t [b, s, c]
// ---------------------------------------------------------------------------
__global__ void tr_p2_k(const float* __restrict__ src) {
    __shared__ float t[32][33];
    int b  = blockIdx.z;
    int s0 = blockIdx.x * 32;
    int c0 = blockIdx.y * 32;
    int tx = threadIdx.x, ty = threadIdx.y;
#pragma unroll
    for (int i = 0; i < 4; i++) {
        int cl = ty + i * 8;
        t[cl][tx] = src[((size_t)b * CIN + (c0 + cl)) * SP + s0 + tx];
    }
    __syncthreads();
#pragma unroll
    for (int i = 0; i < 4; i++) {
        int sl = ty + i * 8;
        g_p2t[((size_t)b * SP + (s0 + sl)) * CIN + c0 + tx] = t[tx][sl];
    }
}

// ---------------------------------------------------------------------------
// Embedding modulation: one warp per (b, output-row j)
// ---------------------------------------------------------------------------
__global__ void emb_k(const float* __restrict__ t_emb, const float* __restrict__ c_emb,
                      const float* __restrict__ tw, const float* __restrict__ tb,
                      const float* __restrict__ cw, const float* __restrict__ cb) {
    int gw   = (blockIdx.x * blockDim.x + threadIdx.x) >> 5;
    int lane = threadIdx.x & 31;
    int b = gw >> 9;
    int j = gw & 511;
    const float* twr = tw + (size_t)j * C1;
    const float* cwr = cw + (size_t)j * C1;
    const float* te  = t_emb + b * C1;
    const float* ce  = c_emb + b * C1;
    int k0 = lane * 8;
    float4 a0 = *(const float4*)(twr + k0);
    float4 a1 = *(const float4*)(twr + k0 + 4);
    float4 b0 = *(const float4*)(cwr + k0);
    float4 b1 = *(const float4*)(cwr + k0 + 4);
    float4 t0 = *(const float4*)(te + k0);
    float4 t1 = *(const float4*)(te + k0 + 4);
    float4 c0 = *(const float4*)(ce + k0);
    float4 c1 = *(const float4*)(ce + k0 + 4);
    float s = a0.x * t0.x + a0.y * t0.y + a0.z * t0.z + a0.w * t0.w
            + a1.x * t1.x + a1.y * t1.y + a1.z * t1.z + a1.w * t1.w
            + b0.x * c0.x + b0.y * c0.y + b0.z * c0.z + b0.w * c0.w
            + b1.x * c1.x + b1.y * c1.y + b1.z * c1.z + b1.w * c1.w;
#pragma unroll
    for (int off = 16; off >= 1; off >>= 1) s += __shfl_xor_sync(0xffffffffu, s, off);
    if (lane == 0) {
        s += tb[j] + cb[j];
        if (j < C1) g_scale[b * C1 + j] = s;
        else        g_shift[b * C1 + (j - C1)] = s;
    }
}

// ---------------------------------------------------------------------------
// 3-NN + inverse-distance interpolation -> stage0 A plane cols [128,384)
// ---------------------------------------------------------------------------
__global__ void knn_k(const float* __restrict__ xyz1, const float* __restrict__ xyz2) {
    __shared__ float4 ref[SP];
    int b = blockIdx.y;
    int n = blockIdx.x * 128 + threadIdx.x;
    for (int s = threadIdx.x; s < SP; s += 128) {
        float x = xyz2[((size_t)b * 3 + 0) * SP + s];
        float y = xyz2[((size_t)b * 3 + 1) * SP + s];
        float z = xyz2[((size_t)b * 3 + 2) * SP + s];
        ref[s] = make_float4(x, y, z, x * x + y * y + z * z);
    }
    __syncthreads();

    float px = xyz1[((size_t)b * 3 + 0) * NP + n];
    float py = xyz1[((size_t)b * 3 + 1) * NP + n];
    float pz = xyz1[((size_t)b * 3 + 2) * NP + n];
    float n1 = px * px + py * py + pz * pz;

    float d0 = 3.4e38f, d1 = 3.4e38f, d2 = 3.4e38f;
    int   i0 = 0, i1 = 0, i2 = 0;
    for (int s = 0; s < SP; s++) {
        float4 r = ref[s];
        float dot = px * r.x + py * r.y + pz * r.z;
        float d = (-2.0f * dot + n1) + r.w;
        if (d < d2) {
            if (d < d1) {
                d2 = d1; i2 = i1;
                if (d < d0) { d1 = d0; i1 = i0; d0 = d; i0 = s; }
                else        { d1 = d;  i1 = s; }
            } else { d2 = d; i2 = s; }
        }
    }

    float r0 = 1.0f / (d0 + 1e-8f);
    float r1 = 1.0f / (d1 + 1e-8f);
    float r2 = 1.0f / (d2 + 1e-8f);
    float rs = r0 + r1 + r2;
    float w0 = r0 / rs, w1 = r1 / rs, w2 = r2 / rs;

    const float4* p0 = (const float4*)&g_p2t[((size_t)b * SP + i0) * CIN];
    const float4* p1 = (const float4*)&g_p2t[((size_t)b * SP + i1) * CIN];
    const float4* p2 = (const float4*)&g_p2t[((size_t)b * SP + i2) * CIN];
    size_t mof = ((size_t)b * NP + n) * C0 + CSK;
#pragma unroll 4
    for (int c = 0; c < CIN / 4; c++) {
        float4 a = p0[c], bq = p1[c], cq = p2[c];
        __half h[4];
        h[0] = __float2half(a.x * w0 + bq.x * w1 + cq.x * w2);
        h[1] = __float2half(a.y * w0 + bq.y * w1 + cq.y * w2);
        h[2] = __float2half(a.z * w0 + bq.z * w1 + cq.z * w2);
        h[3] = __float2half(a.w * w0 + bq.w * w1 + cq.w * w2);
        *(uint2*)(g_A0 + mof + c * 4) = *(uint2*)h;
    }
}

// ---------------------------------------------------------------------------
// Tensor-core GEMM, single-product fp16, 2-stage cp.async pipeline.
//   C[m,o] = sum_k A[m,k]*W[o,k] + bias[o]
// BM=BN=128, BK=32, 256 threads (8 warps: 2m x 4n, 64x32 warp tile).
// ---------------------------------------------------------------------------
constexpr int ASTR = 40;                 // smem row stride (fp16)
constexpr int PL   = 128 * ASTR * 2;     // one plane: 10240 B
constexpr int BUFB = 2 * PL;             // A, W: 20480 B
constexpr int GSM  = 2 * BUFB;           // 40960 B dynamic smem (< 48KB default)

template <int K, int ON, int STAGE>
__global__ __launch_bounds__(256) void gemm_mma(const float* __restrict__ bias) {
    constexpr int NB = K / 32;
    extern __shared__ char smdyn[];

    const __half* Ap = (STAGE == 0) ? g_A0 : (STAGE == 1 ? g_X1 : g_X2);
    const __half* Wp = (STAGE == 0) ? g_W0 : (STAGE == 1 ? g_W1 : g_W2);
    float*        Co = (STAGE == 0) ? g_y1 : (STAGE == 1 ? g_h1 : g_h2);

    const int tid  = threadIdx.x;
    const int m0   = blockIdx.x * 128;
    const int n0   = blockIdx.y * 128;
    const int b    = m0 >> 13;  // NP = 8192
    const int lane = tid & 31;
    const int warp = tid >> 5;
    const int wm   = (warp & 1) * 64;   // warp m-offset
    const int wn   = (warp >> 1) * 32;  // warp n-offset

    const uint32_t sb = sptr(smdyn);

    // cp.async staging: idx = q*256+tid -> row = idx>>2, col8 = (idx&3)*8
    uint32_t soff[2];
    const __half *pA[2], *pW[2];
#pragma unroll
    for (int q = 0; q < 2; q++) {
        int idx = q * 256 + tid;
        int row = idx >> 2, c8 = (idx & 3) * 8;
        soff[q] = (uint32_t)(row * ASTR + c8) * 2;
        pA[q] = Ap + (size_t)(m0 + row) * K + c8;
        pW[q] = Wp + (size_t)(n0 + row) * K + c8;
    }
    auto issue_tile = [&](int kb, int bs) {
        int k0 = kb * 32;
        uint32_t base = sb + bs * BUFB;
#pragma unroll
        for (int q = 0; q < 2; q++) {
            uint32_t d = base + soff[q];
            cp16(d + 0 * PL, pA[q] + k0);
            cp16(d + 1 * PL, pW[q] + k0);
        }
    };

    float c[4][4][4];
#pragma unroll
    for (int i = 0; i < 4; i++)
#pragma unroll
        for (int j = 0; j < 4; j++)
#pragma unroll
            for (int r = 0; r < 4; r++) c[i][j][r] = 0.0f;

    const int lr15 = lane & 15;
    const int lk8  = (lane >> 4) << 3;

    issue_tile(0, 0);
    cp_commit();

    for (int kb = 0; kb < NB; kb++) {
        int bs = kb & 1;
        if (kb + 1 < NB) {
            issue_tile(kb + 1, bs ^ 1);
            cp_commit();
            cp_wait<1>();
        } else {
            cp_wait<0>();
        }
        __syncthreads();

        uint32_t bufbase = sb + bs * BUFB;
        uint32_t aB = bufbase + 0 * PL;
        uint32_t wB = bufbase + 1 * PL;

#pragma unroll
        for (int ks = 0; ks < 32; ks += 16) {
            uint32_t a[4][4], w[4][2];
#pragma unroll
            for (int i = 0; i < 4; i++) {
                uint32_t off = (uint32_t)((wm + i * 16 + lr15) * ASTR + ks + lk8) * 2;
                ldmx4(a[i], aB + off);
            }
#pragma unroll
            for (int p = 0; p < 2; p++) {
                uint32_t off = (uint32_t)((wn + p * 16 + lr15) * ASTR + ks + lk8) * 2;
                uint32_t r[4];
                ldmx4(r, wB + off);
                w[2 * p][0] = r[0]; w[2 * p][1] = r[2];
                w[2 * p + 1][0] = r[1]; w[2 * p + 1][1] = r[3];
            }
#pragma unroll
            for (int i = 0; i < 4; i++)
#pragma unroll
                for (int j = 0; j < 4; j++)
                    mma16816(c[i][j], a[i], w[j]);
        }
        __syncthreads();   // all warps done reading buf bs before it is refilled
    }

    // Epilogue: +bias, store fp32, accumulate GN stats (whole warp -> one group)
    float s = 0.0f, s2 = 0.0f;
#pragma unroll
    for (int i = 0; i < 4; i++) {
#pragma unroll
        for (int j = 0; j < 4; j++) {
            int row = m0 + wm + i * 16 + (lane >> 2);
            int col = n0 + wn + j * 8 + (lane & 3) * 2;
            float b0 = __ldg(bias + col), b1 = __ldg(bias + col + 1);
            float v0 = c[i][j][0] + b0, v1 = c[i][j][1] + b1;
            float v2 = c[i][j][2] + b0, v3 = c[i][j][3] + b1;
            *(float2*)&Co[(size_t)row * ON + col]       = make_float2(v0, v1);
            *(float2*)&Co[(size_t)(row + 8) * ON + col] = make_float2(v2, v3);
            s  += v0 + v1 + v2 + v3;
            s2 += v0 * v0 + v1 * v1 + v2 * v2 + v3 * v3;
        }
    }
#pragma unroll
    for (int off = 16; off >= 1; off >>= 1) {
        s  += __shfl_xor_sync(0xffffffffu, s,  off);
        s2 += __shfl_xor_sync(0xffffffffu, s2, off);
    }
    if (lane == 0) {
        int g = (n0 + wn) / (ON / 8);
        atomicAdd(&g_sum[STAGE * 64 + b * 8 + g], s);
        atomicAdd(&g_sqs[STAGE * 64 + b * 8 + g], s2);
    }
}

// ---------------------------------------------------------------------------
// Finalize GN stats -> per-(b,c) affine coefs: x*a + bb == gn(x)*gw+gb
// ---------------------------------------------------------------------------
template <int STAGE, int CCH>
__global__ void finalize_k(const float* __restrict__ gw, const float* __restrict__ gb) {
    int b = blockIdx.x, c = threadIdx.x;
    int g = c / (CCH / 8);
    float cnt  = (float)(CCH / 8) * (float)NP;
    float mean = g_sum[STAGE * 64 + b * 8 + g] / cnt;
    float var  = g_sqs[STAGE * 64 + b * 8 + g] / cnt - mean * mean;
    float rstd = rsqrtf(var + 1e-5f);
    float a  = rstd * gw[c];
    float bb = gb[c] - mean * a;
    if      (STAGE == 0) { g_cA0[b * CCH + c] = a; g_cB0[b * CCH + c] = bb; }
    else if (STAGE == 1) { g_cA1[b * CCH + c] = a; g_cB1[b * CCH + c] = bb; }
    else                 { g_cA2[b * CCH + c] = a; g_cB2[b * CCH + c] = bb; }
}

// ---------------------------------------------------------------------------
// Final: out[b,c,n] = gn2(h2)*(1+scale)+shift + silu(gn0(y1))  (with transpose)
// ---------------------------------------------------------------------------
__global__ void final_k(float* __restrict__ out) {
    __shared__ float t[32][33];
    int b  = blockIdx.z;
    int n0 = blockIdx.x * 32;
    int c0 = blockIdx.y * 32;
    int tx = threadIdx.x, ty = threadIdx.y;
#pragma unroll
    for (int i = 0; i < 4; i++) {
        int nl = ty + i * 8;
        size_t m = (size_t)b * NP + n0 + nl;
        int c = c0 + tx;
        float h2 = g_h2[m * C1 + c];
        float hn = h2 * g_cA2[b * C1 + c] + g_cB2[b * C1 + c];
        float y1 = g_y1[m * C1 + c];
        float idn = silu_f(y1 * g_cA0[b * C1 + c] + g_cB0[b * C1 + c]);
        float v = hn * (1.0f + g_scale[b * C1 + c]) + g_shift[b * C1 + c] + idn;
        t[nl][tx] = v;
    }
    __syncthreads();
#pragma unroll
    for (int i = 0; i < 4; i++) {
        int cl = ty + i * 8;
        out[((size_t)b * C1 + c0 + cl) * NP + n0 + tx] = t[tx][cl];
    }
}

// ---------------------------------------------------------------------------
// Launch
// ---------------------------------------------------------------------------
extern "C" void kernel_launch(void* const* d_in, const int* in_sizes, int n_in,
                              void* d_out, int out_size) {
    (void)in_sizes; (void)n_in; (void)out_size;
    const float* xyz1    = (const float*)d_in[0];
    const float* points1 = (const float*)d_in[1];
    const float* xyz2    = (const float*)d_in[2];
    const float* points2 = (const float*)d_in[3];
    const float* t_emb   = (const float*)d_in[4];
    const float* c_emb   = (const float*)d_in[5];
    const float* mlp_w   = (const float*)d_in[6];
    const float* mlp_b   = (const float*)d_in[7];
    const float* mlp_gw  = (const float*)d_in[8];
    const float* mlp_gb  = (const float*)d_in[9];
    const float* c1w     = (const float*)d_in[10];
    const float* c1b     = (const float*)d_in[11];
    const float* g1w     = (const float*)d_in[12];
    const float* g1b     = (const float*)d_in[13];
    const float* c2w     = (const float*)d_in[14];
    const float* c2b     = (const float*)d_in[15];
    const float* g2w     = (const float*)d_in[16];
    const float* g2b     = (const float*)d_in[17];
    const float* tw      = (const float*)d_in[18];
    const float* tb      = (const float*)d_in[19];
    const float* cw      = (const float*)d_in[20];
    const float* cb      = (const float*)d_in[21];
    float* out = (float*)d_out;

    zero_k<<<1, 256>>>();
    wsplit_k<0><<<(C1 * C0 / 8 + 255) / 256, 256>>>(mlp_w, C1 * C0 / 8);
    wsplit_k<1><<<(CE * C1 / 8 + 255) / 256, 256>>>(c1w, CE * C1 / 8);
    wsplit_k<2><<<(C1 * CE / 8 + 255) / 256, 256>>>(c2w, C1 * CE / 8);
    tr_p1_k<<<dim3(NP / 32, CSK / 32, BB), dim3(32, 8)>>>(points1);
    tr_p2_k<<<dim3(SP / 32, CIN / 32, BB), dim3(32, 8)>>>(points2);
    emb_k<<<512, 256>>>(t_emb, c_emb, tw, tb, cw, cb);
    knn_k<<<dim3(NP / 128, BB), 128>>>(xyz1, xyz2);

    gemm_mma<C0, C1, 0><<<dim3(MTOT / 128, C1 / 128), 256, GSM>>>(mlp_b);
    finalize_k<0, C1><<<BB, C1>>>(mlp_gw, mlp_gb);
    asplit_k<1><<<MTOT * C1 / 8 / 256, 256>>>();

    gemm_mma<C1, CE, 1><<<dim3(MTOT / 128, CE / 128), 256, GSM>>>(c1b);
    finalize_k<1, CE><<<BB, CE>>>(g1w, g1b);
    asplit_k<2><<<MTOT * CE / 8 / 256, 256>>>();

    gemm_mma<CE, C1, 2><<<dim3(MTOT / 128, C1 / 128), 256, GSM>>>(c2b);
    finalize_k<2, C1><<<BB, C1>>>(g2w, g2b);

    final_k<<<dim3(NP / 32, C1 / 32, BB), dim3(32, 8)>>>(out);
}